// round 7
// baseline (speedup 1.0000x reference)
#include <cuda_runtime.h>
#include <cstdint>

#define NN  100000
#define NE  1600000
#define CH  128
#define LAT 64
#define NBLK_SCAN 98      // ceil(100000/1024)
#define GBLK 782          // ceil(NN/128) gemm blocks

// ---------------- scratch (no allocations allowed) ----------------
__device__ float d_A[(size_t)NN * CH];   // h0 = x @ W1
__device__ float d_B[(size_t)NN * CH];   // g = A * h
__device__ float d_Cb[(size_t)NN * CH];  // h = relu(conv1)
__device__ float d_dis[NN];
__device__ int   d_cnt[NN];
__device__ int   d_off[NN + 1];
__device__ int   d_pos[NN];
__device__ int2  d_adj[NE];
__device__ int   d_blk[128], d_blkoff[128];
__device__ int   d_is64;
// B in per-thread MMA fragment layout: idx = ((kp*16 + j)*32 + lane)*4 + q
// q: {b0(ks=2kp), b1(ks=2kp), b0(ks=2kp+1), b1(ks=2kp+1)}
__device__ float d_F1hi[CH * CH],  d_F1lo[CH * CH];    // W1
__device__ float d_Fmlhi[CH * CH], d_Fmllo[CH * CH];   // [Wmu|Wlv]

// ---------------- tf32 helpers ----------------
__device__ __forceinline__ uint32_t f2tf32(float v) {
    uint32_t r; asm("cvt.rna.tf32.f32 %0, %1;" : "=r"(r) : "f"(v)); return r;
}
__device__ __forceinline__ void split_tf32(float v, uint32_t& hi, uint32_t& lo) {
    hi = f2tf32(v);
    lo = f2tf32(v - __uint_as_float(hi));
}
__device__ __forceinline__ void mma_tf32(float c[4], const uint32_t a[4],
                                         uint32_t b0, uint32_t b1) {
    asm volatile(
        "mma.sync.aligned.m16n8k8.row.col.f32.tf32.tf32.f32 "
        "{%0,%1,%2,%3},{%4,%5,%6,%7},{%8,%9},{%0,%1,%2,%3};"
        : "+f"(c[0]), "+f"(c[1]), "+f"(c[2]), "+f"(c[3])
        : "r"(a[0]), "r"(a[1]), "r"(a[2]), "r"(a[3]), "r"(b0), "r"(b1));
}

// ---------------- W split into fragment layout (one-time, tiny) ----------------
__global__ void k_wsplit(const float* __restrict__ W1,
                         const float* __restrict__ Wmu,
                         const float* __restrict__ Wlv) {
    int i = blockIdx.x * 256 + threadIdx.x;
    if (i >= CH * CH) return;
    int q = i & 3, lane = (i >> 2) & 31, j = (i >> 7) & 15, kp = i >> 11;
    int g = lane >> 2, tig = lane & 3;
    int ks = kp * 2 + (q >> 1);
    int krow = ks * 8 + tig + 4 * (q & 1);
    int col = j * 8 + g;
    uint32_t h, l;
    split_tf32(W1[krow * CH + col], h, l);
    d_F1hi[i] = __uint_as_float(h);
    d_F1lo[i] = __uint_as_float(l);
    float w = (col < 64) ? Wmu[krow * 64 + col] : Wlv[krow * 64 + (col - 64)];
    split_tf32(w, h, l);
    d_Fmlhi[i] = __uint_as_float(h);
    d_Fmllo[i] = __uint_as_float(l);
}

// ---------------- detect width + zero counters ----------------
__global__ void k_detect_zero(const int* __restrict__ ei32) {
    int gid = blockIdx.x * 256 + threadIdx.x;
    if (gid < NN) d_cnt[gid] = 0;
    if (blockIdx.x == 0) {
        __shared__ int any;
        if (threadIdx.x == 0) any = 0;
        __syncthreads();
        for (int i = threadIdx.x; i < 4096; i += 256)
            if (ei32[2 * i + 1] != 0) any = 1;
        __syncthreads();
        if (threadIdx.x == 0) d_is64 = (any == 0) ? 1 : 0;
    }
}
__device__ __forceinline__ int edge_idx(const void* ei, int part, int e) {
    if (d_is64) return (int)((const long long*)ei)[(size_t)part * NE + e];
    return ((const int*)ei)[(size_t)part * NE + e];
}

__global__ void k_hist(const void* __restrict__ ei) {
    int i = blockIdx.x * 256 + threadIdx.x;
    if (i < NE) atomicAdd(&d_cnt[edge_idx(ei, 1, i)], 1);
}

// ---------------- 3xTF32 GEMM mainloop: 128 rows x 128 cols, K=128 ----------
// A staged in swizzled smem (16KB); B fragments streamed from L2 via LDG.128.
__device__ __forceinline__ void gemm_tc_loop(const float* __restrict__ Asrc,
                                             const float4* __restrict__ Fh4,
                                             const float4* __restrict__ Fl4,
                                             int row0, float acc[16][4]) {
    __shared__ float sA[128 * 32];           // XOR-swizzled
    int tid  = threadIdx.x;
    int lane = tid & 31, warp = tid >> 5;
    int g = lane >> 2, tig = lane & 3;
    int ar = warp * 16 + g;
    int amask = 4 * g;

    for (int c = 0; c < 4; c++) {            // K chunk = 32
#pragma unroll
        for (int i = 0; i < 4; i++) {        // stage A tile 128x32, swizzled
            int idx = tid + i * 256;
            int r = idx >> 3, c4 = (idx & 7) * 4;
            int rg = row0 + r; rg = (rg < NN) ? rg : (NN - 1);
            float4 v = *(const float4*)(Asrc + (size_t)rg * CH + c * 32 + c4);
            *(float4*)(sA + r * 32 + (c4 ^ ((r & 7) * 4))) = v;
        }
        __syncthreads();
#pragma unroll
        for (int kpl = 0; kpl < 2; kpl++) {
            int k0 = kpl * 16;
            uint32_t ah0[4], al0[4], ah1[4], al1[4];
            split_tf32(sA[ar * 32 + ((k0 + tig) ^ amask)],           ah0[0], al0[0]);
            split_tf32(sA[(ar + 8) * 32 + ((k0 + tig) ^ amask)],     ah0[1], al0[1]);
            split_tf32(sA[ar * 32 + ((k0 + tig + 4) ^ amask)],       ah0[2], al0[2]);
            split_tf32(sA[(ar + 8) * 32 + ((k0 + tig + 4) ^ amask)], ah0[3], al0[3]);
            split_tf32(sA[ar * 32 + ((k0 + 8 + tig) ^ amask)],           ah1[0], al1[0]);
            split_tf32(sA[(ar + 8) * 32 + ((k0 + 8 + tig) ^ amask)],     ah1[1], al1[1]);
            split_tf32(sA[ar * 32 + ((k0 + 8 + tig + 4) ^ amask)],       ah1[2], al1[2]);
            split_tf32(sA[(ar + 8) * 32 + ((k0 + 8 + tig + 4) ^ amask)], ah1[3], al1[3]);
            const float4* bh = Fh4 + (size_t)((c * 2 + kpl) * 16) * 32 + lane;
            const float4* bl = Fl4 + (size_t)((c * 2 + kpl) * 16) * 32 + lane;
#pragma unroll
            for (int j = 0; j < 16; j++) {
                float4 vh = __ldg(bh + j * 32);
                float4 vl = __ldg(bl + j * 32);
                mma_tf32(acc[j], ah0, __float_as_uint(vh.x), __float_as_uint(vh.y));
                mma_tf32(acc[j], ah0, __float_as_uint(vl.x), __float_as_uint(vl.y));
                mma_tf32(acc[j], al0, __float_as_uint(vh.x), __float_as_uint(vh.y));
                mma_tf32(acc[j], ah1, __float_as_uint(vh.z), __float_as_uint(vh.w));
                mma_tf32(acc[j], ah1, __float_as_uint(vl.z), __float_as_uint(vl.w));
                mma_tf32(acc[j], al1, __float_as_uint(vh.z), __float_as_uint(vh.w));
            }
        }
        __syncthreads();
    }
}

// ---------------- GEMM1: d_A = x @ W1 (tensor cores) ----------------
__global__ __launch_bounds__(256, 2) void k_gemm1_tc(const float* __restrict__ x) {
    float acc[16][4];
#pragma unroll
    for (int j = 0; j < 16; j++) acc[j][0] = acc[j][1] = acc[j][2] = acc[j][3] = 0.f;
    int row0 = blockIdx.x * 128;
    gemm_tc_loop(x, (const float4*)d_F1hi, (const float4*)d_F1lo, row0, acc);

    int lane = threadIdx.x & 31, warp = threadIdx.x >> 5;
    int g = lane >> 2, tig = lane & 3;
    int r0 = row0 + warp * 16 + g, r1 = r0 + 8;
#pragma unroll
    for (int j = 0; j < 16; j++) {
        int col = j * 8 + 2 * tig;
        if (r0 < NN) *(float2*)(d_A + (size_t)r0 * CH + col) = make_float2(acc[j][0], acc[j][1]);
        if (r1 < NN) *(float2*)(d_A + (size_t)r1 * CH + col) = make_float2(acc[j][2], acc[j][3]);
    }
}

// ---------------- prefix sum (dis fused) ----------------
__global__ void k_scan_local() {
    __shared__ int s[1024];
    int tid = threadIdx.x;
    int gid = blockIdx.x * 1024 + tid;
    int v = (gid < NN) ? d_cnt[gid] : 0;
    if (gid < NN) d_dis[gid] = rsqrtf((float)v + 1.0f);
    s[tid] = v;
    __syncthreads();
    for (int o = 1; o < 1024; o <<= 1) {
        int t = (tid >= o) ? s[tid - o] : 0;
        __syncthreads();
        s[tid] += t;
        __syncthreads();
    }
    if (gid < NN) d_off[gid] = s[tid] - v;
    if (tid == 1023) d_blk[blockIdx.x] = s[1023];
}
__global__ void k_scan_blk() {
    __shared__ int s[128];
    int tid = threadIdx.x;
    int v = (tid < NBLK_SCAN) ? d_blk[tid] : 0;
    s[tid] = v;
    __syncthreads();
    for (int o = 1; o < 128; o <<= 1) {
        int t = (tid >= o) ? s[tid - o] : 0;
        __syncthreads();
        s[tid] += t;
        __syncthreads();
    }
    d_blkoff[tid] = s[tid] - v;
}
__global__ void k_scan_add() {
    int gid = blockIdx.x * 1024 + threadIdx.x;
    if (gid < NN) {
        int o = d_off[gid] + d_blkoff[blockIdx.x];
        d_off[gid] = o;
        d_pos[gid] = o;
    }
    if (gid == 0) d_off[NN] = NE;
}

__global__ void k_fill(const void* __restrict__ ei) {
    int e = blockIdx.x * 256 + threadIdx.x;
    if (e >= NE) return;
    int r = edge_idx(ei, 0, e);
    int c = edge_idx(ei, 1, e);
    int p = atomicAdd(&d_pos[c], 1);
    d_adj[p] = make_int2(r, __float_as_int(d_dis[r]));
}

// ---------------- CSR gather: one warp per node ----------------
__global__ __launch_bounds__(256) void k_gather(const float* __restrict__ b1,
                                                int phase) {
    int node = (blockIdx.x * 256 + threadIdx.x) >> 5;
    if (node >= NN) return;
    int lane = threadIdx.x & 31;
    const float* __restrict__ src = phase ? d_Cb : d_A;
    float* __restrict__ dst       = phase ? d_B  : d_Cb;
    int beg = d_off[node], end = d_off[node + 1];
    float dc = d_dis[node];

    float4 acc = ((const float4*)(src + (size_t)node * CH))[lane];
    acc.x *= dc; acc.y *= dc; acc.z *= dc; acc.w *= dc;

    for (int base = beg; base < end; base += 32) {
        int t = base + lane;
        int2 pr = (t < end) ? d_adj[t] : make_int2(0, 0);
        int n = min(32, end - base);
#pragma unroll 8
        for (int k = 0; k < n; k++) {
            int   j = __shfl_sync(0xffffffffu, pr.x, k);
            float w = __int_as_float(__shfl_sync(0xffffffffu, pr.y, k));
            float4 v = ((const float4*)(src + (size_t)j * CH))[lane];
            acc.x = fmaf(w, v.x, acc.x);
            acc.y = fmaf(w, v.y, acc.y);
            acc.z = fmaf(w, v.z, acc.z);
            acc.w = fmaf(w, v.w, acc.w);
        }
    }
    acc.x *= dc; acc.y *= dc; acc.z *= dc; acc.w *= dc;

    if (phase == 0) {
        float4 bias = ((const float4*)b1)[lane];
        acc.x = fmaxf(acc.x + bias.x, 0.f);
        acc.y = fmaxf(acc.y + bias.y, 0.f);
        acc.z = fmaxf(acc.z + bias.z, 0.f);
        acc.w = fmaxf(acc.w + bias.w, 0.f);
    }
    ((float4*)(dst + (size_t)node * CH))[lane] = acc;
}

// ---------------- final: [mu|lv] = g @ [Wmu|Wlv] (tensor) + reparam ----------
__global__ __launch_bounds__(256, 2) void k_final_tc(const float* __restrict__ bmu,
                                                     const float* __restrict__ blv,
                                                     const float* __restrict__ eps,
                                                     float* __restrict__ out) {
    float acc[16][4];
#pragma unroll
    for (int j = 0; j < 16; j++) acc[j][0] = acc[j][1] = acc[j][2] = acc[j][3] = 0.f;
    int row0 = blockIdx.x * 128;
    gemm_tc_loop(d_B, (const float4*)d_Fmlhi, (const float4*)d_Fmllo, row0, acc);

    int lane = threadIdx.x & 31, warp = threadIdx.x >> 5;
    int g = lane >> 2, tig = lane & 3;
    int r0 = row0 + warp * 16 + g, r1 = r0 + 8;

    float* out_z  = out;
    float* out_mu = out + (size_t)NN * LAT;
    float* out_lv = out + 2 * (size_t)NN * LAT;

#pragma unroll
    for (int j = 0; j < 8; j++) {               // mu tiles; lv = tile j+8
        int col = j * 8 + 2 * tig;
        float2 bm = *(const float2*)(bmu + col);
        float2 bl = *(const float2*)(blv + col);
        if (r0 < NN) {
            float m0 = acc[j][0] + bm.x,     m1 = acc[j][1] + bm.y;
            float l0 = acc[j + 8][0] + bl.x, l1 = acc[j + 8][1] + bl.y;
            float2 ev = *(const float2*)(eps + (size_t)r0 * LAT + col);
            float z0 = m0 + ev.x * expf(0.5f * l0);
            float z1 = m1 + ev.y * expf(0.5f * l1);
            size_t o = (size_t)r0 * LAT + col;
            *(float2*)(out_mu + o) = make_float2(m0, m1);
            *(float2*)(out_lv + o) = make_float2(l0, l1);
            *(float2*)(out_z  + o) = make_float2(z0, z1);
        }
        if (r1 < NN) {
            float m0 = acc[j][2] + bm.x,     m1 = acc[j][3] + bm.y;
            float l0 = acc[j + 8][2] + bl.x, l1 = acc[j + 8][3] + bl.y;
            float2 ev = *(const float2*)(eps + (size_t)r1 * LAT + col);
            float z0 = m0 + ev.x * expf(0.5f * l0);
            float z1 = m1 + ev.y * expf(0.5f * l1);
            size_t o = (size_t)r1 * LAT + col;
            *(float2*)(out_mu + o) = make_float2(m0, m1);
            *(float2*)(out_lv + o) = make_float2(l0, l1);
            *(float2*)(out_z  + o) = make_float2(z0, z1);
        }
    }
}

// ---------------- launch ----------------
extern "C" void kernel_launch(void* const* d_in, const int* in_sizes, int n_in,
                              void* d_out, int out_size) {
    const float* x   = (const float*)d_in[0];
    const void*  ei  = d_in[1];
    const float* W1  = (const float*)d_in[2];
    const float* b1  = (const float*)d_in[3];
    const float* Wmu = (const float*)d_in[4];
    const float* bmu = (const float*)d_in[5];
    const float* Wlv = (const float*)d_in[6];
    const float* blv = (const float*)d_in[7];
    const float* eps = (const float*)d_in[8];
    float* out = (float*)d_out;

    k_wsplit<<<64, 256>>>(W1, Wmu, Wlv);                      // 1
    k_detect_zero<<<(NN + 255) / 256, 256>>>((const int*)ei); // 2
    k_hist<<<(NE + 255) / 256, 256>>>(ei);                    // 3
    k_gemm1_tc<<<GBLK, 256>>>(x);                             // 4 (profiled slot)
    k_scan_local<<<NBLK_SCAN, 1024>>>();                      // 5
    k_scan_blk<<<1, 128>>>();                                 // 6
    k_scan_add<<<NBLK_SCAN, 1024>>>();                        // 7
    k_fill<<<(NE + 255) / 256, 256>>>(ei);                    // 8

    k_gather<<<(NN * 32 + 255) / 256, 256>>>(b1, 0);          // 9
    k_gather<<<(NN * 32 + 255) / 256, 256>>>(b1, 1);          // 10

    k_final_tc<<<GBLK, 256>>>(bmu, blv, eps, out);            // 11
}

// round 8
// speedup vs baseline: 1.0008x; 1.0008x over previous
#include <cuda_runtime.h>
#include <cstdint>

#define NN  100000
#define NE  1600000
#define CH  128
#define LAT 64
#define NBLK_SCAN 98      // ceil(100000/1024)
#define GBLK 782          // ceil(NN/128) gemm blocks

// ---------------- scratch (no allocations allowed) ----------------
__device__ float d_A[(size_t)NN * CH];   // h0 = x @ W1
__device__ float d_B[(size_t)NN * CH];   // g = A * h
__device__ float d_Cb[(size_t)NN * CH];  // h = relu(conv1)
__device__ float d_dis[NN];
__device__ int   d_cnt[NN];
__device__ int   d_off[NN + 1];
__device__ int   d_pos[NN];
__device__ int2  d_adj[NE];
__device__ int   d_blk[128], d_blkoff[128];
__device__ int   d_is64;
// B in per-thread MMA fragment layout: idx = ((kp*16 + j)*32 + lane)*4 + q
// q: {b0(ks=2kp), b1(ks=2kp), b0(ks=2kp+1), b1(ks=2kp+1)}
__device__ float d_F1hi[CH * CH],  d_F1lo[CH * CH];    // W1
__device__ float d_Fmlhi[CH * CH], d_Fmllo[CH * CH];   // [Wmu|Wlv]

// ---------------- tf32 helpers ----------------
__device__ __forceinline__ uint32_t f2tf32(float v) {
    uint32_t r; asm("cvt.rna.tf32.f32 %0, %1;" : "=r"(r) : "f"(v)); return r;
}
__device__ __forceinline__ void split_tf32(float v, uint32_t& hi, uint32_t& lo) {
    hi = f2tf32(v);
    lo = f2tf32(v - __uint_as_float(hi));
}
__device__ __forceinline__ void mma_tf32(float c[4], const uint32_t a[4],
                                         uint32_t b0, uint32_t b1) {
    asm volatile(
        "mma.sync.aligned.m16n8k8.row.col.f32.tf32.tf32.f32 "
        "{%0,%1,%2,%3},{%4,%5,%6,%7},{%8,%9},{%0,%1,%2,%3};"
        : "+f"(c[0]), "+f"(c[1]), "+f"(c[2]), "+f"(c[3])
        : "r"(a[0]), "r"(a[1]), "r"(a[2]), "r"(a[3]), "r"(b0), "r"(b1));
}

// ---------------- W split into fragment layout (one-time, tiny) ----------------
__global__ void k_wsplit(const float* __restrict__ W1,
                         const float* __restrict__ Wmu,
                         const float* __restrict__ Wlv) {
    int i = blockIdx.x * 256 + threadIdx.x;
    if (i >= CH * CH) return;
    int q = i & 3, lane = (i >> 2) & 31, j = (i >> 7) & 15, kp = i >> 11;
    int g = lane >> 2, tig = lane & 3;
    int ks = kp * 2 + (q >> 1);
    int krow = ks * 8 + tig + 4 * (q & 1);
    int col = j * 8 + g;
    uint32_t h, l;
    split_tf32(W1[krow * CH + col], h, l);
    d_F1hi[i] = __uint_as_float(h);
    d_F1lo[i] = __uint_as_float(l);
    float w = (col < 64) ? Wmu[krow * 64 + col] : Wlv[krow * 64 + (col - 64)];
    split_tf32(w, h, l);
    d_Fmlhi[i] = __uint_as_float(h);
    d_Fmllo[i] = __uint_as_float(l);
}

// ---------------- detect width + zero counters ----------------
__global__ void k_detect_zero(const int* __restrict__ ei32) {
    int gid = blockIdx.x * 256 + threadIdx.x;
    if (gid < NN) d_cnt[gid] = 0;
    if (blockIdx.x == 0) {
        __shared__ int any;
        if (threadIdx.x == 0) any = 0;
        __syncthreads();
        for (int i = threadIdx.x; i < 4096; i += 256)
            if (ei32[2 * i + 1] != 0) any = 1;
        __syncthreads();
        if (threadIdx.x == 0) d_is64 = (any == 0) ? 1 : 0;
    }
}
__device__ __forceinline__ int edge_idx(const void* ei, int part, int e) {
    if (d_is64) return (int)((const long long*)ei)[(size_t)part * NE + e];
    return ((const int*)ei)[(size_t)part * NE + e];
}

__global__ void k_hist(const void* __restrict__ ei) {
    int i = blockIdx.x * 256 + threadIdx.x;
    if (i < NE) atomicAdd(&d_cnt[edge_idx(ei, 1, i)], 1);
}

// ---------------- 3xTF32 GEMM mainloop, 512 threads ----------
// 128 rows x 128 cols, K=128. 16 warps: warp (wr,wc) owns rows wr*16..+15,
// cols wc*64 + j*8 (j=0..7). acc = 32 regs/thread.
// sPool: [0,4096) swizzled A; [4096,8192) B hi frags; [8192,12288) B lo frags.
__device__ __forceinline__ void gemm_tc_loop(float* sPool,
                                             const float* __restrict__ Asrc,
                                             const float4* __restrict__ Fh4,
                                             const float4* __restrict__ Fl4,
                                             int row0, float acc[8][4]) {
    float*  sA  = sPool;
    float4* sBh = (float4*)(sPool + 4096);
    float4* sBl = (float4*)(sPool + 8192);
    int tid  = threadIdx.x;
    int lane = tid & 31, warp = tid >> 5;
    int g = lane >> 2, tig = lane & 3;
    int wr = warp >> 1, wc = warp & 1;
    int ar = wr * 16 + g;
    int amask = 4 * g;

    for (int c = 0; c < 4; c++) {            // K chunk = 32
#pragma unroll
        for (int i = 0; i < 2; i++) {        // stage A tile 128x32, swizzled
            int idx = tid + i * 512;
            int r = idx >> 3, c4 = (idx & 7) * 4;
            int rg = row0 + r; rg = (rg < NN) ? rg : (NN - 1);
            float4 v = *(const float4*)(Asrc + (size_t)rg * CH + c * 32 + c4);
            *(float4*)(sA + r * 32 + (c4 ^ ((r & 7) * 4))) = v;
        }
#pragma unroll
        for (int i = 0; i < 2; i++) {        // stage B frags (coalesced)
            int t = tid + i * 512;           // 1024 float4 per array per chunk
            int kpl = t >> 9, jj = (t >> 5) & 15, ln = t & 31;
            int sidx = (jj * 2 + kpl) * 32 + ln;
            sBh[sidx] = Fh4[c * 1024 + t];
            sBl[sidx] = Fl4[c * 1024 + t];
        }
        __syncthreads();
#pragma unroll
        for (int kpl = 0; kpl < 2; kpl++) {
            int k0 = kpl * 16;
            uint32_t ah0[4], al0[4], ah1[4], al1[4];
            split_tf32(sA[ar * 32 + ((k0 + tig) ^ amask)],           ah0[0], al0[0]);
            split_tf32(sA[(ar + 8) * 32 + ((k0 + tig) ^ amask)],     ah0[1], al0[1]);
            split_tf32(sA[ar * 32 + ((k0 + tig + 4) ^ amask)],       ah0[2], al0[2]);
            split_tf32(sA[(ar + 8) * 32 + ((k0 + tig + 4) ^ amask)], ah0[3], al0[3]);
            split_tf32(sA[ar * 32 + ((k0 + 8 + tig) ^ amask)],           ah1[0], al1[0]);
            split_tf32(sA[(ar + 8) * 32 + ((k0 + 8 + tig) ^ amask)],     ah1[1], al1[1]);
            split_tf32(sA[ar * 32 + ((k0 + 8 + tig + 4) ^ amask)],       ah1[2], al1[2]);
            split_tf32(sA[(ar + 8) * 32 + ((k0 + 8 + tig + 4) ^ amask)], ah1[3], al1[3]);
#pragma unroll
            for (int jj = 0; jj < 8; jj++) {
                int jg = wc * 8 + jj;
                float4 bh = sBh[(jg * 2 + kpl) * 32 + lane];
                float4 bl = sBl[(jg * 2 + kpl) * 32 + lane];
                mma_tf32(acc[jj], ah0, __float_as_uint(bh.x), __float_as_uint(bh.y));
                mma_tf32(acc[jj], ah0, __float_as_uint(bl.x), __float_as_uint(bl.y));
                mma_tf32(acc[jj], al0, __float_as_uint(bh.x), __float_as_uint(bh.y));
                mma_tf32(acc[jj], ah1, __float_as_uint(bh.z), __float_as_uint(bh.w));
                mma_tf32(acc[jj], ah1, __float_as_uint(bl.z), __float_as_uint(bl.w));
                mma_tf32(acc[jj], al1, __float_as_uint(bh.z), __float_as_uint(bh.w));
            }
        }
        __syncthreads();
    }
}

// ---------------- GEMM1: d_A = x @ W1 (tensor cores, 512 thr) ----------------
__global__ __launch_bounds__(512, 1) void k_gemm1_tc(const float* __restrict__ x) {
    __shared__ float sPool[12288];
    float acc[8][4];
#pragma unroll
    for (int j = 0; j < 8; j++) acc[j][0] = acc[j][1] = acc[j][2] = acc[j][3] = 0.f;
    int row0 = blockIdx.x * 128;
    gemm_tc_loop(sPool, x, (const float4*)d_F1hi, (const float4*)d_F1lo, row0, acc);

    int lane = threadIdx.x & 31, warp = threadIdx.x >> 5;
    int g = lane >> 2, tig = lane & 3;
    int wr = warp >> 1, wc = warp & 1;
    int r0 = row0 + wr * 16 + g, r1 = r0 + 8;
#pragma unroll
    for (int jj = 0; jj < 8; jj++) {
        int col = wc * 64 + jj * 8 + 2 * tig;
        if (r0 < NN) *(float2*)(d_A + (size_t)r0 * CH + col) = make_float2(acc[jj][0], acc[jj][1]);
        if (r1 < NN) *(float2*)(d_A + (size_t)r1 * CH + col) = make_float2(acc[jj][2], acc[jj][3]);
    }
}

// ---------------- prefix sum (dis fused) ----------------
__global__ void k_scan_local() {
    __shared__ int s[1024];
    int tid = threadIdx.x;
    int gid = blockIdx.x * 1024 + tid;
    int v = (gid < NN) ? d_cnt[gid] : 0;
    if (gid < NN) d_dis[gid] = rsqrtf((float)v + 1.0f);
    s[tid] = v;
    __syncthreads();
    for (int o = 1; o < 1024; o <<= 1) {
        int t = (tid >= o) ? s[tid - o] : 0;
        __syncthreads();
        s[tid] += t;
        __syncthreads();
    }
    if (gid < NN) d_off[gid] = s[tid] - v;
    if (tid == 1023) d_blk[blockIdx.x] = s[1023];
}
__global__ void k_scan_blk() {
    __shared__ int s[128];
    int tid = threadIdx.x;
    int v = (tid < NBLK_SCAN) ? d_blk[tid] : 0;
    s[tid] = v;
    __syncthreads();
    for (int o = 1; o < 128; o <<= 1) {
        int t = (tid >= o) ? s[tid - o] : 0;
        __syncthreads();
        s[tid] += t;
        __syncthreads();
    }
    d_blkoff[tid] = s[tid] - v;
}
__global__ void k_scan_add() {
    int gid = blockIdx.x * 1024 + threadIdx.x;
    if (gid < NN) {
        int o = d_off[gid] + d_blkoff[blockIdx.x];
        d_off[gid] = o;
        d_pos[gid] = o;
    }
    if (gid == 0) d_off[NN] = NE;
}

__global__ void k_fill(const void* __restrict__ ei) {
    int e = blockIdx.x * 256 + threadIdx.x;
    if (e >= NE) return;
    int r = edge_idx(ei, 0, e);
    int c = edge_idx(ei, 1, e);
    int p = atomicAdd(&d_pos[c], 1);
    d_adj[p] = make_int2(r, __float_as_int(d_dis[r]));
}

// ---------------- CSR gather: one warp per node ----------------
__global__ __launch_bounds__(256) void k_gather(const float* __restrict__ b1,
                                                int phase) {
    int node = (blockIdx.x * 256 + threadIdx.x) >> 5;
    if (node >= NN) return;
    int lane = threadIdx.x & 31;
    const float* __restrict__ src = phase ? d_Cb : d_A;
    float* __restrict__ dst       = phase ? d_B  : d_Cb;
    int beg = d_off[node], end = d_off[node + 1];
    float dc = d_dis[node];

    float4 acc = ((const float4*)(src + (size_t)node * CH))[lane];
    acc.x *= dc; acc.y *= dc; acc.z *= dc; acc.w *= dc;

    for (int base = beg; base < end; base += 32) {
        int t = base + lane;
        int2 pr = (t < end) ? d_adj[t] : make_int2(0, 0);
        int n = min(32, end - base);
#pragma unroll 8
        for (int k = 0; k < n; k++) {
            int   j = __shfl_sync(0xffffffffu, pr.x, k);
            float w = __int_as_float(__shfl_sync(0xffffffffu, pr.y, k));
            float4 v = ((const float4*)(src + (size_t)j * CH))[lane];
            acc.x = fmaf(w, v.x, acc.x);
            acc.y = fmaf(w, v.y, acc.y);
            acc.z = fmaf(w, v.z, acc.z);
            acc.w = fmaf(w, v.w, acc.w);
        }
    }
    acc.x *= dc; acc.y *= dc; acc.z *= dc; acc.w *= dc;

    if (phase == 0) {
        float4 bias = ((const float4*)b1)[lane];
        acc.x = fmaxf(acc.x + bias.x, 0.f);
        acc.y = fmaxf(acc.y + bias.y, 0.f);
        acc.z = fmaxf(acc.z + bias.z, 0.f);
        acc.w = fmaxf(acc.w + bias.w, 0.f);
    }
    ((float4*)(dst + (size_t)node * CH))[lane] = acc;
}

// ---------------- final: [mu|lv] = g @ [Wmu|Wlv] + reparam (512 thr) --------
// wc=0 warps hold mu (cols 0..63), wc=1 warps hold lv (cols 64..127).
// lv exchanged through smem (stride 66 to avoid bank conflicts).
__global__ __launch_bounds__(512, 1) void k_final_tc(const float* __restrict__ bmu,
                                                     const float* __restrict__ blv,
                                                     const float* __restrict__ eps,
                                                     float* __restrict__ out) {
    __shared__ float sPool[12288];
    float acc[8][4];
#pragma unroll
    for (int j = 0; j < 8; j++) acc[j][0] = acc[j][1] = acc[j][2] = acc[j][3] = 0.f;
    int row0 = blockIdx.x * 128;
    gemm_tc_loop(sPool, d_B, (const float4*)d_Fmlhi, (const float4*)d_Fmllo, row0, acc);

    int lane = threadIdx.x & 31, warp = threadIdx.x >> 5;
    int g = lane >> 2, tig = lane & 3;
    int wr = warp >> 1, wc = warp & 1;
    int lr0 = wr * 16 + g, lr1 = lr0 + 8;      // local rows
    int r0 = row0 + lr0, r1 = row0 + lr1;

    float* out_z  = out;
    float* out_mu = out + (size_t)NN * LAT;
    float* out_lv = out + 2 * (size_t)NN * LAT;
    float* ex = sPool;                          // 128 x 66 lv exchange

    if (wc == 1) {                              // lv warps: bias, write gmem + smem
#pragma unroll
        for (int jj = 0; jj < 8; jj++) {
            int col = jj * 8 + 2 * tig;         // local 0..63
            float2 bl = *(const float2*)(blv + col);
            float l00 = acc[jj][0] + bl.x, l01 = acc[jj][1] + bl.y;
            float l10 = acc[jj][2] + bl.x, l11 = acc[jj][3] + bl.y;
            ex[lr0 * 66 + col] = l00; ex[lr0 * 66 + col + 1] = l01;
            ex[lr1 * 66 + col] = l10; ex[lr1 * 66 + col + 1] = l11;
            if (r0 < NN) *(float2*)(out_lv + (size_t)r0 * LAT + col) = make_float2(l00, l01);
            if (r1 < NN) *(float2*)(out_lv + (size_t)r1 * LAT + col) = make_float2(l10, l11);
        }
    }
    __syncthreads();
    if (wc == 0) {                              // mu warps: bias, z, write gmem
#pragma unroll
        for (int jj = 0; jj < 8; jj++) {
            int col = jj * 8 + 2 * tig;
            float2 bm = *(const float2*)(bmu + col);
            float m00 = acc[jj][0] + bm.x, m01 = acc[jj][1] + bm.y;
            float m10 = acc[jj][2] + bm.x, m11 = acc[jj][3] + bm.y;
            float l00 = ex[lr0 * 66 + col], l01 = ex[lr0 * 66 + col + 1];
            float l10 = ex[lr1 * 66 + col], l11 = ex[lr1 * 66 + col + 1];
            if (r0 < NN) {
                float2 ev = *(const float2*)(eps + (size_t)r0 * LAT + col);
                float z0 = m00 + ev.x * expf(0.5f * l00);
                float z1 = m01 + ev.y * expf(0.5f * l01);
                *(float2*)(out_mu + (size_t)r0 * LAT + col) = make_float2(m00, m01);
                *(float2*)(out_z  + (size_t)r0 * LAT + col) = make_float2(z0, z1);
            }
            if (r1 < NN) {
                float2 ev = *(const float2*)(eps + (size_t)r1 * LAT + col);
                float z0 = m10 + ev.x * expf(0.5f * l10);
                float z1 = m11 + ev.y * expf(0.5f * l11);
                *(float2*)(out_mu + (size_t)r1 * LAT + col) = make_float2(m10, m11);
                *(float2*)(out_z  + (size_t)r1 * LAT + col) = make_float2(z0, z1);
            }
        }
    }
}

// ---------------- launch ----------------
extern "C" void kernel_launch(void* const* d_in, const int* in_sizes, int n_in,
                              void* d_out, int out_size) {
    const float* x   = (const float*)d_in[0];
    const void*  ei  = d_in[1];
    const float* W1  = (const float*)d_in[2];
    const float* b1  = (const float*)d_in[3];
    const float* Wmu = (const float*)d_in[4];
    const float* bmu = (const float*)d_in[5];
    const float* Wlv = (const float*)d_in[6];
    const float* blv = (const float*)d_in[7];
    const float* eps = (const float*)d_in[8];
    float* out = (float*)d_out;

    k_wsplit<<<64, 256>>>(W1, Wmu, Wlv);                      // 1
    k_detect_zero<<<(NN + 255) / 256, 256>>>((const int*)ei); // 2
    k_hist<<<(NE + 255) / 256, 256>>>(ei);                    // 3
    k_gemm1_tc<<<GBLK, 512>>>(x);                             // 4 (profiled slot)
    k_scan_local<<<NBLK_SCAN, 1024>>>();                      // 5
    k_scan_blk<<<1, 128>>>();                                 // 6
    k_scan_add<<<NBLK_SCAN, 1024>>>();                        // 7
    k_fill<<<(NE + 255) / 256, 256>>>(ei);                    // 8

    k_gather<<<(NN * 32 + 255) / 256, 256>>>(b1, 0);          // 9
    k_gather<<<(NN * 32 + 255) / 256, 256>>>(b1, 1);          // 10

    k_final_tc<<<GBLK, 512>>>(bmu, blv, eps, out);            // 11
}

// round 9
// speedup vs baseline: 1.1881x; 1.1872x over previous
#include <cuda_runtime.h>
#include <cstdint>

#define NN  100000
#define NE  1600000
#define CH  128
#define LAT 64
#define NBLK_SCAN 98      // ceil(100000/1024)
#define GBLK 782          // ceil(NN/128) gemm blocks

// ---------------- scratch (no allocations allowed) ----------------
__device__ float d_A[(size_t)NN * CH];   // h0 = x @ W1
__device__ float d_B[(size_t)NN * CH];   // g = A * h
__device__ float d_Cb[(size_t)NN * CH];  // h = relu(conv1)
__device__ float d_dis[NN];
__device__ int   d_cnt[NN];
__device__ int   d_off[NN + 1];
__device__ int   d_pos[NN];
__device__ int2  d_adj[NE];
__device__ int   d_blk[128], d_blkoff[128];
__device__ int   d_is64;
// B in per-thread MMA fragment layout: idx = ((kp*16 + j)*32 + lane)*4 + q
// q: {b0(k8 lo), b1(k8 lo), b0(k8 hi), b1(k8 hi)} within kp chunk of 16 k-rows
__device__ float d_F1hi[CH * CH],  d_F1lo[CH * CH];    // W1
__device__ float d_Fmlhi[CH * CH], d_Fmllo[CH * CH];   // [Wmu|Wlv]

// ---------------- tf32 helpers ----------------
__device__ __forceinline__ uint32_t f2tf32(float v) {
    uint32_t r; asm("cvt.rna.tf32.f32 %0, %1;" : "=r"(r) : "f"(v)); return r;
}
__device__ __forceinline__ void split_tf32(float v, uint32_t& hi, uint32_t& lo) {
    hi = f2tf32(v);
    lo = f2tf32(v - __uint_as_float(hi));
}
__device__ __forceinline__ void mma_tf32(float c[4], const uint32_t a[4],
                                         uint32_t b0, uint32_t b1) {
    asm volatile(
        "mma.sync.aligned.m16n8k8.row.col.f32.tf32.tf32.f32 "
        "{%0,%1,%2,%3},{%4,%5,%6,%7},{%8,%9},{%0,%1,%2,%3};"
        : "+f"(c[0]), "+f"(c[1]), "+f"(c[2]), "+f"(c[3])
        : "r"(a[0]), "r"(a[1]), "r"(a[2]), "r"(a[3]), "r"(b0), "r"(b1));
}
__device__ __forceinline__ uint32_t smem_u32(const void* p) {
    return (uint32_t)__cvta_generic_to_shared(p);
}
__device__ __forceinline__ void cpa16(uint32_t dst, const void* src) {
    asm volatile("cp.async.cg.shared.global [%0], [%1], 16;" :: "r"(dst), "l"(src));
}

// ---------------- W split into fragment layout (one-time, tiny) ----------------
__global__ void k_wsplit(const float* __restrict__ W1,
                         const float* __restrict__ Wmu,
                         const float* __restrict__ Wlv) {
    int i = blockIdx.x * 256 + threadIdx.x;
    if (i >= CH * CH) return;
    int q = i & 3, lane = (i >> 2) & 31, j = (i >> 7) & 15, kp = i >> 11;
    int g = lane >> 2, tig = lane & 3;
    int ks = kp * 2 + (q >> 1);
    int krow = ks * 8 + tig + 4 * (q & 1);
    int col = j * 8 + g;
    uint32_t h, l;
    split_tf32(W1[krow * CH + col], h, l);
    d_F1hi[i] = __uint_as_float(h);
    d_F1lo[i] = __uint_as_float(l);
    float w = (col < 64) ? Wmu[krow * 64 + col] : Wlv[krow * 64 + (col - 64)];
    split_tf32(w, h, l);
    d_Fmlhi[i] = __uint_as_float(h);
    d_Fmllo[i] = __uint_as_float(l);
}

// ---------------- detect width + zero counters ----------------
__global__ void k_detect_zero(const int* __restrict__ ei32) {
    int gid = blockIdx.x * 256 + threadIdx.x;
    if (gid < NN) d_cnt[gid] = 0;
    if (blockIdx.x == 0) {
        __shared__ int any;
        if (threadIdx.x == 0) any = 0;
        __syncthreads();
        for (int i = threadIdx.x; i < 4096; i += 256)
            if (ei32[2 * i + 1] != 0) any = 1;
        __syncthreads();
        if (threadIdx.x == 0) d_is64 = (any == 0) ? 1 : 0;
    }
}
__device__ __forceinline__ int edge_idx(const void* ei, int part, int e) {
    if (d_is64) return (int)((const long long*)ei)[(size_t)part * NE + e];
    return ((const int*)ei)[(size_t)part * NE + e];
}

__global__ void k_hist(const void* __restrict__ ei) {
    int i = blockIdx.x * 256 + threadIdx.x;
    if (i < NE) atomicAdd(&d_cnt[edge_idx(ei, 1, i)], 1);
}

// ---------------- 3xTF32 GEMM, cp.async 2-stage pipeline ----------
// 128 rows x 128 cols, K=128 in 8 chunks of K=16. 256 threads, 8 warps,
// warp owns rows warp*16..+15, all 128 cols. acc[16][4].
// sPool floats: [0,4096) A (2 bufs x 128rows x 16); [4096,8192) Bhi; [8192,12288) Blo.
// A slot-swizzle: float4 slot s of row r stored at slot s ^ ((r>>1)&3).
__device__ __forceinline__ void gemm_tc_loop(float* sPool,
                                             const float* __restrict__ Asrc,
                                             const float4* __restrict__ Fh4,
                                             const float4* __restrict__ Fl4,
                                             int row0, float acc[16][4]) {
    int tid  = threadIdx.x;
    int lane = tid & 31, warp = tid >> 5;
    int g = lane >> 2, tig = lane & 3;
    int ar = warp * 16 + g;
    uint32_t sbase = smem_u32(sPool);

    auto copy_chunk = [&](int c, int buf) {
        uint32_t aBuf = sbase + (buf * 2048) * 4;
        uint32_t hBuf = sbase + (4096 + buf * 2048) * 4;
        uint32_t lBuf = sbase + (8192 + buf * 2048) * 4;
#pragma unroll
        for (int i = 0; i < 2; i++) {        // A: 512 float4 (128 rows x 4 slots)
            int idx = tid + i * 256;
            int r = idx >> 2, s = idx & 3;
            int rg = row0 + r; rg = (rg < NN) ? rg : (NN - 1);
            const float* src = Asrc + (size_t)rg * CH + c * 16 + s * 4;
            int phys = r * 16 + ((s ^ ((r >> 1) & 3)) << 2);
            cpa16(aBuf + phys * 4, src);
        }
#pragma unroll
        for (int i = 0; i < 2; i++) {        // B frags: 512 float4 each
            int t = tid + i * 256;
            cpa16(hBuf + t * 16, Fh4 + (size_t)c * 512 + t);
            cpa16(lBuf + t * 16, Fl4 + (size_t)c * 512 + t);
        }
        asm volatile("cp.async.commit_group;" ::: "memory");
    };

    copy_chunk(0, 0);
    for (int c = 0; c < 8; c++) {
        if (c < 7) {
            copy_chunk(c + 1, (c + 1) & 1);
            asm volatile("cp.async.wait_group 1;" ::: "memory");
        } else {
            asm volatile("cp.async.wait_group 0;" ::: "memory");
        }
        __syncthreads();

        const float*  sA  = sPool + (c & 1) * 2048;
        const float4* sBh = (const float4*)(sPool + 4096 + (c & 1) * 2048);
        const float4* sBl = (const float4*)(sPool + 8192 + (c & 1) * 2048);
#define LDA(r, s) sA[(r) * 16 + (((((s) ^ (((r) >> 1) & 3))) << 2) | tig)]
        uint32_t ah0[4], al0[4], ah1[4], al1[4];
        split_tf32(LDA(ar, 0),     ah0[0], al0[0]);
        split_tf32(LDA(ar + 8, 0), ah0[1], al0[1]);
        split_tf32(LDA(ar, 1),     ah0[2], al0[2]);
        split_tf32(LDA(ar + 8, 1), ah0[3], al0[3]);
        split_tf32(LDA(ar, 2),     ah1[0], al1[0]);
        split_tf32(LDA(ar + 8, 2), ah1[1], al1[1]);
        split_tf32(LDA(ar, 3),     ah1[2], al1[2]);
        split_tf32(LDA(ar + 8, 3), ah1[3], al1[3]);
#undef LDA
#pragma unroll
        for (int j = 0; j < 16; j++) {
            float4 bh = sBh[j * 32 + lane];
            float4 bl = sBl[j * 32 + lane];
            mma_tf32(acc[j], ah0, __float_as_uint(bh.x), __float_as_uint(bh.y));
            mma_tf32(acc[j], ah0, __float_as_uint(bl.x), __float_as_uint(bl.y));
            mma_tf32(acc[j], al0, __float_as_uint(bh.x), __float_as_uint(bh.y));
            mma_tf32(acc[j], ah1, __float_as_uint(bh.z), __float_as_uint(bh.w));
            mma_tf32(acc[j], ah1, __float_as_uint(bl.z), __float_as_uint(bl.w));
            mma_tf32(acc[j], al1, __float_as_uint(bh.z), __float_as_uint(bh.w));
        }
        __syncthreads();
    }
}

// ---------------- GEMM1: d_A = x @ W1 (tensor cores) ----------------
__global__ __launch_bounds__(256, 2) void k_gemm1_tc(const float* __restrict__ x) {
    __shared__ float sPool[12288];
    float acc[16][4];
#pragma unroll
    for (int j = 0; j < 16; j++) acc[j][0] = acc[j][1] = acc[j][2] = acc[j][3] = 0.f;
    int row0 = blockIdx.x * 128;
    gemm_tc_loop(sPool, x, (const float4*)d_F1hi, (const float4*)d_F1lo, row0, acc);

    int lane = threadIdx.x & 31, warp = threadIdx.x >> 5;
    int g = lane >> 2, tig = lane & 3;
    int r0 = row0 + warp * 16 + g, r1 = r0 + 8;
#pragma unroll
    for (int j = 0; j < 16; j++) {
        int col = j * 8 + 2 * tig;
        if (r0 < NN) *(float2*)(d_A + (size_t)r0 * CH + col) = make_float2(acc[j][0], acc[j][1]);
        if (r1 < NN) *(float2*)(d_A + (size_t)r1 * CH + col) = make_float2(acc[j][2], acc[j][3]);
    }
}

// ---------------- prefix sum (dis fused) ----------------
__global__ void k_scan_local() {
    __shared__ int s[1024];
    int tid = threadIdx.x;
    int gid = blockIdx.x * 1024 + tid;
    int v = (gid < NN) ? d_cnt[gid] : 0;
    if (gid < NN) d_dis[gid] = rsqrtf((float)v + 1.0f);
    s[tid] = v;
    __syncthreads();
    for (int o = 1; o < 1024; o <<= 1) {
        int t = (tid >= o) ? s[tid - o] : 0;
        __syncthreads();
        s[tid] += t;
        __syncthreads();
    }
    if (gid < NN) d_off[gid] = s[tid] - v;
    if (tid == 1023) d_blk[blockIdx.x] = s[1023];
}
__global__ void k_scan_blk() {
    __shared__ int s[128];
    int tid = threadIdx.x;
    int v = (tid < NBLK_SCAN) ? d_blk[tid] : 0;
    s[tid] = v;
    __syncthreads();
    for (int o = 1; o < 128; o <<= 1) {
        int t = (tid >= o) ? s[tid - o] : 0;
        __syncthreads();
        s[tid] += t;
        __syncthreads();
    }
    d_blkoff[tid] = s[tid] - v;
}
__global__ void k_scan_add() {
    int gid = blockIdx.x * 1024 + threadIdx.x;
    if (gid < NN) {
        int o = d_off[gid] + d_blkoff[blockIdx.x];
        d_off[gid] = o;
        d_pos[gid] = o;
    }
    if (gid == 0) d_off[NN] = NE;
}

__global__ void k_fill(const void* __restrict__ ei) {
    int e = blockIdx.x * 256 + threadIdx.x;
    if (e >= NE) return;
    int r = edge_idx(ei, 0, e);
    int c = edge_idx(ei, 1, e);
    int p = atomicAdd(&d_pos[c], 1);
    d_adj[p] = make_int2(r, __float_as_int(d_dis[r]));
}

// ---------------- CSR gather: one warp per node ----------------
__global__ __launch_bounds__(256) void k_gather(const float* __restrict__ b1,
                                                int phase) {
    int node = (blockIdx.x * 256 + threadIdx.x) >> 5;
    if (node >= NN) return;
    int lane = threadIdx.x & 31;
    const float* __restrict__ src = phase ? d_Cb : d_A;
    float* __restrict__ dst       = phase ? d_B  : d_Cb;
    int beg = d_off[node], end = d_off[node + 1];
    float dc = d_dis[node];

    float4 acc = ((const float4*)(src + (size_t)node * CH))[lane];
    acc.x *= dc; acc.y *= dc; acc.z *= dc; acc.w *= dc;

    for (int base = beg; base < end; base += 32) {
        int t = base + lane;
        int2 pr = (t < end) ? d_adj[t] : make_int2(0, 0);
        int n = min(32, end - base);
#pragma unroll 8
        for (int k = 0; k < n; k++) {
            int   j = __shfl_sync(0xffffffffu, pr.x, k);
            float w = __int_as_float(__shfl_sync(0xffffffffu, pr.y, k));
            float4 v = ((const float4*)(src + (size_t)j * CH))[lane];
            acc.x = fmaf(w, v.x, acc.x);
            acc.y = fmaf(w, v.y, acc.y);
            acc.z = fmaf(w, v.z, acc.z);
            acc.w = fmaf(w, v.w, acc.w);
        }
    }
    acc.x *= dc; acc.y *= dc; acc.z *= dc; acc.w *= dc;

    if (phase == 0) {
        float4 bias = ((const float4*)b1)[lane];
        acc.x = fmaxf(acc.x + bias.x, 0.f);
        acc.y = fmaxf(acc.y + bias.y, 0.f);
        acc.z = fmaxf(acc.z + bias.z, 0.f);
        acc.w = fmaxf(acc.w + bias.w, 0.f);
    }
    ((float4*)(dst + (size_t)node * CH))[lane] = acc;
}

// ---------------- final: [mu|lv] = g @ [Wmu|Wlv] (tensor) + reparam ----------
__global__ __launch_bounds__(256, 2) void k_final_tc(const float* __restrict__ bmu,
                                                     const float* __restrict__ blv,
                                                     const float* __restrict__ eps,
                                                     float* __restrict__ out) {
    __shared__ float sPool[12288];
    float acc[16][4];
#pragma unroll
    for (int j = 0; j < 16; j++) acc[j][0] = acc[j][1] = acc[j][2] = acc[j][3] = 0.f;
    int row0 = blockIdx.x * 128;
    gemm_tc_loop(sPool, d_B, (const float4*)d_Fmlhi, (const float4*)d_Fmllo, row0, acc);

    int lane = threadIdx.x & 31, warp = threadIdx.x >> 5;
    int g = lane >> 2, tig = lane & 3;
    int r0 = row0 + warp * 16 + g, r1 = r0 + 8;

    float* out_z  = out;
    float* out_mu = out + (size_t)NN * LAT;
    float* out_lv = out + 2 * (size_t)NN * LAT;

#pragma unroll
    for (int j = 0; j < 8; j++) {               // mu tiles; lv = tile j+8
        int col = j * 8 + 2 * tig;
        float2 bm = *(const float2*)(bmu + col);
        float2 bl = *(const float2*)(blv + col);
        if (r0 < NN) {
            float m0 = acc[j][0] + bm.x,     m1 = acc[j][1] + bm.y;
            float l0 = acc[j + 8][0] + bl.x, l1 = acc[j + 8][1] + bl.y;
            float2 ev = *(const float2*)(eps + (size_t)r0 * LAT + col);
            float z0 = m0 + ev.x * expf(0.5f * l0);
            float z1 = m1 + ev.y * expf(0.5f * l1);
            size_t o = (size_t)r0 * LAT + col;
            *(float2*)(out_mu + o) = make_float2(m0, m1);
            *(float2*)(out_lv + o) = make_float2(l0, l1);
            *(float2*)(out_z  + o) = make_float2(z0, z1);
        }
        if (r1 < NN) {
            float m0 = acc[j][2] + bm.x,     m1 = acc[j][3] + bm.y;
            float l0 = acc[j + 8][2] + bl.x, l1 = acc[j + 8][3] + bl.y;
            float2 ev = *(const float2*)(eps + (size_t)r1 * LAT + col);
            float z0 = m0 + ev.x * expf(0.5f * l0);
            float z1 = m1 + ev.y * expf(0.5f * l1);
            size_t o = (size_t)r1 * LAT + col;
            *(float2*)(out_mu + o) = make_float2(m0, m1);
            *(float2*)(out_lv + o) = make_float2(l0, l1);
            *(float2*)(out_z  + o) = make_float2(z0, z1);
        }
    }
}

// ---------------- launch ----------------
extern "C" void kernel_launch(void* const* d_in, const int* in_sizes, int n_in,
                              void* d_out, int out_size) {
    const float* x   = (const float*)d_in[0];
    const void*  ei  = d_in[1];
    const float* W1  = (const float*)d_in[2];
    const float* b1  = (const float*)d_in[3];
    const float* Wmu = (const float*)d_in[4];
    const float* bmu = (const float*)d_in[5];
    const float* Wlv = (const float*)d_in[6];
    const float* blv = (const float*)d_in[7];
    const float* eps = (const float*)d_in[8];
    float* out = (float*)d_out;

    k_wsplit<<<64, 256>>>(W1, Wmu, Wlv);                      // 1
    k_detect_zero<<<(NN + 255) / 256, 256>>>((const int*)ei); // 2
    k_hist<<<(NE + 255) / 256, 256>>>(ei);                    // 3
    k_gemm1_tc<<<GBLK, 256>>>(x);                             // 4 (profiled slot)
    k_scan_local<<<NBLK_SCAN, 1024>>>();                      // 5
    k_scan_blk<<<1, 128>>>();                                 // 6
    k_scan_add<<<NBLK_SCAN, 1024>>>();                        // 7
    k_fill<<<(NE + 255) / 256, 256>>>(ei);                    // 8

    k_gather<<<(NN * 32 + 255) / 256, 256>>>(b1, 0);          // 9
    k_gather<<<(NN * 32 + 255) / 256, 256>>>(b1, 1);          // 10

    k_final_tc<<<GBLK, 256>>>(bmu, blv, eps, out);            // 11
}

// round 10
// speedup vs baseline: 1.2541x; 1.0555x over previous
#include <cuda_runtime.h>
#include <cstdint>

#define NN  100000
#define NE  1600000
#define CH  128
#define LAT 64
#define NBLK_SCAN 98      // ceil(100000/1024)
#define GBLK 782          // ceil(NN/128) gemm blocks

// ---------------- scratch (no allocations allowed) ----------------
__device__ float d_A[(size_t)NN * CH];   // h0 = x @ W1
__device__ float d_B[(size_t)NN * CH];   // g = A * h
__device__ float d_Cb[(size_t)NN * CH];  // h = relu(conv1)
__device__ float d_dis[NN];
__device__ int   d_cnt[NN];
__device__ int   d_off[NN + 1];
__device__ int   d_pos[NN];
__device__ int2  d_adj[NE];
__device__ int   d_blk[128], d_blkoff[128];
__device__ int   d_is64;
// B in per-thread MMA fragment layout: idx = ((kp*16 + j)*32 + lane)*4 + q
__device__ float d_F1hi[CH * CH],  d_F1lo[CH * CH];    // W1
__device__ float d_Fmlhi[CH * CH], d_Fmllo[CH * CH];   // [Wmu|Wlv]

// ---------------- tf32 helpers ----------------
__device__ __forceinline__ uint32_t f2tf32(float v) {
    uint32_t r; asm("cvt.rna.tf32.f32 %0, %1;" : "=r"(r) : "f"(v)); return r;
}
__device__ __forceinline__ void split_tf32(float v, uint32_t& hi, uint32_t& lo) {
    hi = f2tf32(v);
    lo = f2tf32(v - __uint_as_float(hi));
}
__device__ __forceinline__ void mma_tf32(float c[4], const uint32_t a[4],
                                         uint32_t b0, uint32_t b1) {
    asm volatile(
        "mma.sync.aligned.m16n8k8.row.col.f32.tf32.tf32.f32 "
        "{%0,%1,%2,%3},{%4,%5,%6,%7},{%8,%9},{%0,%1,%2,%3};"
        : "+f"(c[0]), "+f"(c[1]), "+f"(c[2]), "+f"(c[3])
        : "r"(a[0]), "r"(a[1]), "r"(a[2]), "r"(a[3]), "r"(b0), "r"(b1));
}
__device__ __forceinline__ uint32_t smem_u32(const void* p) {
    return (uint32_t)__cvta_generic_to_shared(p);
}
__device__ __forceinline__ void cpa16(uint32_t dst, const void* src) {
    asm volatile("cp.async.cg.shared.global [%0], [%1], 16;" :: "r"(dst), "l"(src));
}

// ---------------- W split into fragment layout (one-time, tiny) ----------------
__global__ void k_wsplit(const float* __restrict__ W1,
                         const float* __restrict__ Wmu,
                         const float* __restrict__ Wlv) {
    int i = blockIdx.x * 256 + threadIdx.x;
    if (i >= CH * CH) return;
    int q = i & 3, lane = (i >> 2) & 31, j = (i >> 7) & 15, kp = i >> 11;
    int g = lane >> 2, tig = lane & 3;
    int ks = kp * 2 + (q >> 1);
    int krow = ks * 8 + tig + 4 * (q & 1);
    int col = j * 8 + g;
    uint32_t h, l;
    split_tf32(W1[krow * CH + col], h, l);
    d_F1hi[i] = __uint_as_float(h);
    d_F1lo[i] = __uint_as_float(l);
    float w = (col < 64) ? Wmu[krow * 64 + col] : Wlv[krow * 64 + (col - 64)];
    split_tf32(w, h, l);
    d_Fmlhi[i] = __uint_as_float(h);
    d_Fmllo[i] = __uint_as_float(l);
}

// ---------------- detect width + zero counters ----------------
__global__ void k_detect_zero(const int* __restrict__ ei32) {
    int gid = blockIdx.x * 256 + threadIdx.x;
    if (gid < NN) d_cnt[gid] = 0;
    if (blockIdx.x == 0) {
        __shared__ int any;
        if (threadIdx.x == 0) any = 0;
        __syncthreads();
        for (int i = threadIdx.x; i < 4096; i += 256)
            if (ei32[2 * i + 1] != 0) any = 1;
        __syncthreads();
        if (threadIdx.x == 0) d_is64 = (any == 0) ? 1 : 0;
    }
}
__device__ __forceinline__ int edge_idx(const void* ei, int part, int e) {
    if (d_is64) return (int)((const long long*)ei)[(size_t)part * NE + e];
    return ((const int*)ei)[(size_t)part * NE + e];
}

__global__ void k_hist(const void* __restrict__ ei) {
    int i = blockIdx.x * 256 + threadIdx.x;
    if (i < NE) atomicAdd(&d_cnt[edge_idx(ei, 1, i)], 1);
}

// ---------------- 3xTF32 GEMM, cp.async 2-stage pipeline ----------
__device__ __forceinline__ void gemm_tc_loop(float* sPool,
                                             const float* __restrict__ Asrc,
                                             const float4* __restrict__ Fh4,
                                             const float4* __restrict__ Fl4,
                                             int row0, float acc[16][4]) {
    int tid  = threadIdx.x;
    int lane = tid & 31, warp = tid >> 5;
    int g = lane >> 2, tig = lane & 3;
    int ar = warp * 16 + g;
    uint32_t sbase = smem_u32(sPool);

    auto copy_chunk = [&](int c, int buf) {
        uint32_t aBuf = sbase + (buf * 2048) * 4;
        uint32_t hBuf = sbase + (4096 + buf * 2048) * 4;
        uint32_t lBuf = sbase + (8192 + buf * 2048) * 4;
#pragma unroll
        for (int i = 0; i < 2; i++) {        // A: 512 float4 (128 rows x 4 slots)
            int idx = tid + i * 256;
            int r = idx >> 2, s = idx & 3;
            int rg = row0 + r; rg = (rg < NN) ? rg : (NN - 1);
            const float* src = Asrc + (size_t)rg * CH + c * 16 + s * 4;
            int phys = r * 16 + ((s ^ ((r >> 1) & 3)) << 2);
            cpa16(aBuf + phys * 4, src);
        }
#pragma unroll
        for (int i = 0; i < 2; i++) {        // B frags: 512 float4 each
            int t = tid + i * 256;
            cpa16(hBuf + t * 16, Fh4 + (size_t)c * 512 + t);
            cpa16(lBuf + t * 16, Fl4 + (size_t)c * 512 + t);
        }
        asm volatile("cp.async.commit_group;" ::: "memory");
    };

    copy_chunk(0, 0);
    for (int c = 0; c < 8; c++) {
        if (c < 7) {
            copy_chunk(c + 1, (c + 1) & 1);
            asm volatile("cp.async.wait_group 1;" ::: "memory");
        } else {
            asm volatile("cp.async.wait_group 0;" ::: "memory");
        }
        __syncthreads();

        const float*  sA  = sPool + (c & 1) * 2048;
        const float4* sBh = (const float4*)(sPool + 4096 + (c & 1) * 2048);
        const float4* sBl = (const float4*)(sPool + 8192 + (c & 1) * 2048);
#define LDA(r, s) sA[(r) * 16 + (((((s) ^ (((r) >> 1) & 3))) << 2) | tig)]
        uint32_t ah0[4], al0[4], ah1[4], al1[4];
        split_tf32(LDA(ar, 0),     ah0[0], al0[0]);
        split_tf32(LDA(ar + 8, 0), ah0[1], al0[1]);
        split_tf32(LDA(ar, 1),     ah0[2], al0[2]);
        split_tf32(LDA(ar + 8, 1), ah0[3], al0[3]);
        split_tf32(LDA(ar, 2),     ah1[0], al1[0]);
        split_tf32(LDA(ar + 8, 2), ah1[1], al1[1]);
        split_tf32(LDA(ar, 3),     ah1[2], al1[2]);
        split_tf32(LDA(ar + 8, 3), ah1[3], al1[3]);
#undef LDA
#pragma unroll
        for (int j = 0; j < 16; j++) {
            float4 bh = sBh[j * 32 + lane];
            float4 bl = sBl[j * 32 + lane];
            mma_tf32(acc[j], ah0, __float_as_uint(bh.x), __float_as_uint(bh.y));
            mma_tf32(acc[j], ah0, __float_as_uint(bl.x), __float_as_uint(bl.y));
            mma_tf32(acc[j], al0, __float_as_uint(bh.x), __float_as_uint(bh.y));
            mma_tf32(acc[j], ah1, __float_as_uint(bh.z), __float_as_uint(bh.w));
            mma_tf32(acc[j], ah1, __float_as_uint(bl.z), __float_as_uint(bl.w));
            mma_tf32(acc[j], al1, __float_as_uint(bh.z), __float_as_uint(bh.w));
        }
        __syncthreads();
    }
}

// ---------------- GEMM1: d_A = x @ W1 (tensor cores) ----------------
__global__ __launch_bounds__(256, 2) void k_gemm1_tc(const float* __restrict__ x) {
    __shared__ float sPool[12288];
    float acc[16][4];
#pragma unroll
    for (int j = 0; j < 16; j++) acc[j][0] = acc[j][1] = acc[j][2] = acc[j][3] = 0.f;
    int row0 = blockIdx.x * 128;
    gemm_tc_loop(sPool, x, (const float4*)d_F1hi, (const float4*)d_F1lo, row0, acc);

    int lane = threadIdx.x & 31, warp = threadIdx.x >> 5;
    int g = lane >> 2, tig = lane & 3;
    int r0 = row0 + warp * 16 + g, r1 = r0 + 8;
#pragma unroll
    for (int j = 0; j < 16; j++) {
        int col = j * 8 + 2 * tig;
        if (r0 < NN) *(float2*)(d_A + (size_t)r0 * CH + col) = make_float2(acc[j][0], acc[j][1]);
        if (r1 < NN) *(float2*)(d_A + (size_t)r1 * CH + col) = make_float2(acc[j][2], acc[j][3]);
    }
}

// ---------------- prefix sum (dis fused) ----------------
__global__ void k_scan_local() {
    __shared__ int s[1024];
    int tid = threadIdx.x;
    int gid = blockIdx.x * 1024 + tid;
    int v = (gid < NN) ? d_cnt[gid] : 0;
    if (gid < NN) d_dis[gid] = rsqrtf((float)v + 1.0f);
    s[tid] = v;
    __syncthreads();
    for (int o = 1; o < 1024; o <<= 1) {
        int t = (tid >= o) ? s[tid - o] : 0;
        __syncthreads();
        s[tid] += t;
        __syncthreads();
    }
    if (gid < NN) d_off[gid] = s[tid] - v;
    if (tid == 1023) d_blk[blockIdx.x] = s[1023];
}
__global__ void k_scan_blk() {
    __shared__ int s[128];
    int tid = threadIdx.x;
    int v = (tid < NBLK_SCAN) ? d_blk[tid] : 0;
    s[tid] = v;
    __syncthreads();
    for (int o = 1; o < 128; o <<= 1) {
        int t = (tid >= o) ? s[tid - o] : 0;
        __syncthreads();
        s[tid] += t;
        __syncthreads();
    }
    d_blkoff[tid] = s[tid] - v;
}
__global__ void k_scan_add() {
    int gid = blockIdx.x * 1024 + threadIdx.x;
    if (gid < NN) {
        int o = d_off[gid] + d_blkoff[blockIdx.x];
        d_off[gid] = o;
        d_pos[gid] = o;
    }
    if (gid == 0) d_off[NN] = NE;
}

__global__ void k_fill(const void* __restrict__ ei) {
    int e = blockIdx.x * 256 + threadIdx.x;
    if (e >= NE) return;
    int r = edge_idx(ei, 0, e);
    int c = edge_idx(ei, 1, e);
    int p = atomicAdd(&d_pos[c], 1);
    d_adj[p] = make_int2(r, __float_as_int(d_dis[r]));
}

// ---------------- CSR gather: one warp per node ----------------
__global__ __launch_bounds__(256) void k_gather(const float* __restrict__ b1,
                                                int phase) {
    int node = (blockIdx.x * 256 + threadIdx.x) >> 5;
    if (node >= NN) return;
    int lane = threadIdx.x & 31;
    const float* __restrict__ src = phase ? d_Cb : d_A;
    float* __restrict__ dst       = phase ? d_B  : d_Cb;
    int beg = d_off[node], end = d_off[node + 1];
    float dc = d_dis[node];

    float4 acc = ((const float4*)(src + (size_t)node * CH))[lane];
    acc.x *= dc; acc.y *= dc; acc.z *= dc; acc.w *= dc;

    for (int base = beg; base < end; base += 32) {
        int t = base + lane;
        int2 pr = (t < end) ? d_adj[t] : make_int2(0, 0);
        int n = min(32, end - base);
#pragma unroll 8
        for (int k = 0; k < n; k++) {
            int   j = __shfl_sync(0xffffffffu, pr.x, k);
            float w = __int_as_float(__shfl_sync(0xffffffffu, pr.y, k));
            float4 v = ((const float4*)(src + (size_t)j * CH))[lane];
            acc.x = fmaf(w, v.x, acc.x);
            acc.y = fmaf(w, v.y, acc.y);
            acc.z = fmaf(w, v.z, acc.z);
            acc.w = fmaf(w, v.w, acc.w);
        }
    }
    acc.x *= dc; acc.y *= dc; acc.z *= dc; acc.w *= dc;

    if (phase == 0) {
        float4 bias = ((const float4*)b1)[lane];
        acc.x = fmaxf(acc.x + bias.x, 0.f);
        acc.y = fmaxf(acc.y + bias.y, 0.f);
        acc.z = fmaxf(acc.z + bias.z, 0.f);
        acc.w = fmaxf(acc.w + bias.w, 0.f);
    }
    ((float4*)(dst + (size_t)node * CH))[lane] = acc;
}

// ---------------- final: [mu|lv] = g @ [Wmu|Wlv] (tensor) + reparam ----------
__global__ __launch_bounds__(256, 2) void k_final_tc(const float* __restrict__ bmu,
                                                     const float* __restrict__ blv,
                                                     const float* __restrict__ eps,
                                                     float* __restrict__ out) {
    __shared__ float sPool[12288];
    float acc[16][4];
#pragma unroll
    for (int j = 0; j < 16; j++) acc[j][0] = acc[j][1] = acc[j][2] = acc[j][3] = 0.f;
    int row0 = blockIdx.x * 128;
    gemm_tc_loop(sPool, d_B, (const float4*)d_Fmlhi, (const float4*)d_Fmllo, row0, acc);

    int lane = threadIdx.x & 31, warp = threadIdx.x >> 5;
    int g = lane >> 2, tig = lane & 3;
    int r0 = row0 + warp * 16 + g, r1 = r0 + 8;

    float* out_z  = out;
    float* out_mu = out + (size_t)NN * LAT;
    float* out_lv = out + 2 * (size_t)NN * LAT;

#pragma unroll
    for (int j = 0; j < 8; j++) {               // mu tiles; lv = tile j+8
        int col = j * 8 + 2 * tig;
        float2 bm = *(const float2*)(bmu + col);
        float2 bl = *(const float2*)(blv + col);
        if (r0 < NN) {
            float m0 = acc[j][0] + bm.x,     m1 = acc[j][1] + bm.y;
            float l0 = acc[j + 8][0] + bl.x, l1 = acc[j + 8][1] + bl.y;
            float2 ev = *(const float2*)(eps + (size_t)r0 * LAT + col);
            float z0 = m0 + ev.x * expf(0.5f * l0);
            float z1 = m1 + ev.y * expf(0.5f * l1);
            size_t o = (size_t)r0 * LAT + col;
            *(float2*)(out_mu + o) = make_float2(m0, m1);
            *(float2*)(out_lv + o) = make_float2(l0, l1);
            *(float2*)(out_z  + o) = make_float2(z0, z1);
        }
        if (r1 < NN) {
            float m0 = acc[j][2] + bm.x,     m1 = acc[j][3] + bm.y;
            float l0 = acc[j + 8][2] + bl.x, l1 = acc[j + 8][3] + bl.y;
            float2 ev = *(const float2*)(eps + (size_t)r1 * LAT + col);
            float z0 = m0 + ev.x * expf(0.5f * l0);
            float z1 = m1 + ev.y * expf(0.5f * l1);
            size_t o = (size_t)r1 * LAT + col;
            *(float2*)(out_mu + o) = make_float2(m0, m1);
            *(float2*)(out_lv + o) = make_float2(l0, l1);
            *(float2*)(out_z  + o) = make_float2(z0, z1);
        }
    }
}

// ---------------- launch: fork [wsplit->gemm1] parallel to CSR build ---------
extern "C" void kernel_launch(void* const* d_in, const int* in_sizes, int n_in,
                              void* d_out, int out_size) {
    const float* x   = (const float*)d_in[0];
    const void*  ei  = d_in[1];
    const float* W1  = (const float*)d_in[2];
    const float* b1  = (const float*)d_in[3];
    const float* Wmu = (const float*)d_in[4];
    const float* bmu = (const float*)d_in[5];
    const float* Wlv = (const float*)d_in[6];
    const float* blv = (const float*)d_in[7];
    const float* eps = (const float*)d_in[8];
    float* out = (float*)d_out;

    // One-time host-side resources (no device memory allocation).
    static cudaStream_t s2 = nullptr;
    static cudaEvent_t eFork = nullptr, eJoin = nullptr;
    if (s2 == nullptr) {
        cudaStreamCreateWithFlags(&s2, cudaStreamNonBlocking);
        cudaEventCreateWithFlags(&eFork, cudaEventDisableTiming);
        cudaEventCreateWithFlags(&eJoin, cudaEventDisableTiming);
    }

    // fork: GEMM branch on s2
    cudaEventRecord(eFork, 0);
    cudaStreamWaitEvent(s2, eFork, 0);
    k_wsplit<<<64, 256, 0, s2>>>(W1, Wmu, Wlv);
    k_gemm1_tc<<<GBLK, 256, 0, s2>>>(x);
    cudaEventRecord(eJoin, s2);

    // CSR build on main stream (independent of GEMM branch)
    k_detect_zero<<<(NN + 255) / 256, 256>>>((const int*)ei);
    k_hist<<<(NE + 255) / 256, 256>>>(ei);
    k_scan_local<<<NBLK_SCAN, 1024>>>();
    k_scan_blk<<<1, 128>>>();
    k_scan_add<<<NBLK_SCAN, 1024>>>();
    k_fill<<<(NE + 255) / 256, 256>>>(ei);

    // join: gathers need both d_A (s2) and CSR (main)
    cudaStreamWaitEvent(0, eJoin, 0);
    k_gather<<<(NN * 32 + 255) / 256, 256>>>(b1, 0);
    k_gather<<<(NN * 32 + 255) / 256, 256>>>(b1, 1);
    k_final_tc<<<GBLK, 256>>>(bmu, blv, eps, out);
}

// round 11
// speedup vs baseline: 1.5591x; 1.2432x over previous
#include <cuda_runtime.h>
#include <cuda_fp16.h>
#include <cstdint>

#define NN  100000
#define NE  1600000
#define CH  128
#define LAT 64
#define NBLK_SCAN 98      // ceil(100000/1024)
#define GBLK 782          // ceil(NN/128) gemm blocks

// ---------------- scratch (no allocations allowed) ----------------
__device__ __half d_A[(size_t)NN * CH];   // h0 = x @ W1 (fp16)
__device__ __half d_Cb[(size_t)NN * CH];  // h = relu(conv1) (fp16)
__device__ float  d_B[(size_t)NN * CH];   // g = A * h (fp32, feeds final GEMM)
__device__ float  d_dis[NN];
__device__ int    d_cnt[NN];
__device__ int    d_off[NN + 1];
__device__ int    d_pos[NN];
__device__ int2   d_adj[NE];
__device__ int    d_blk[128], d_blkoff[128];
__device__ int    d_is64;
// B in per-thread MMA fragment layout: idx = ((kp*16 + j)*32 + lane)*4 + q
__device__ float d_F1hi[CH * CH],  d_F1lo[CH * CH];    // W1
__device__ float d_Fmlhi[CH * CH], d_Fmllo[CH * CH];   // [Wmu|Wlv]

// ---------------- tf32 / fp16 helpers ----------------
__device__ __forceinline__ uint32_t f2tf32(float v) {
    uint32_t r; asm("cvt.rna.tf32.f32 %0, %1;" : "=r"(r) : "f"(v)); return r;
}
__device__ __forceinline__ void split_tf32(float v, uint32_t& hi, uint32_t& lo) {
    hi = f2tf32(v);
    lo = f2tf32(v - __uint_as_float(hi));
}
__device__ __forceinline__ void mma_tf32(float c[4], const uint32_t a[4],
                                         uint32_t b0, uint32_t b1) {
    asm volatile(
        "mma.sync.aligned.m16n8k8.row.col.f32.tf32.tf32.f32 "
        "{%0,%1,%2,%3},{%4,%5,%6,%7},{%8,%9},{%0,%1,%2,%3};"
        : "+f"(c[0]), "+f"(c[1]), "+f"(c[2]), "+f"(c[3])
        : "r"(a[0]), "r"(a[1]), "r"(a[2]), "r"(a[3]), "r"(b0), "r"(b1));
}
__device__ __forceinline__ uint32_t smem_u32(const void* p) {
    return (uint32_t)__cvta_generic_to_shared(p);
}
__device__ __forceinline__ void cpa16(uint32_t dst, const void* src) {
    asm volatile("cp.async.cg.shared.global [%0], [%1], 16;" :: "r"(dst), "l"(src));
}
__device__ __forceinline__ float4 ld4h(const __half* p) {
    uint2 raw = *(const uint2*)p;
    __half2 a = *reinterpret_cast<__half2*>(&raw.x);
    __half2 b = *reinterpret_cast<__half2*>(&raw.y);
    float2 fa = __half22float2(a), fb = __half22float2(b);
    return make_float4(fa.x, fa.y, fb.x, fb.y);
}
__device__ __forceinline__ void st4h(__half* p, float4 v) {
    __half2 a = __floats2half2_rn(v.x, v.y);
    __half2 b = __floats2half2_rn(v.z, v.w);
    uint2 raw;
    raw.x = *reinterpret_cast<uint32_t*>(&a);
    raw.y = *reinterpret_cast<uint32_t*>(&b);
    *(uint2*)p = raw;
}

// ---------------- W split into fragment layout (one-time, tiny) ----------------
__global__ void k_wsplit(const float* __restrict__ W1,
                         const float* __restrict__ Wmu,
                         const float* __restrict__ Wlv) {
    int i = blockIdx.x * 256 + threadIdx.x;
    if (i >= CH * CH) return;
    int q = i & 3, lane = (i >> 2) & 31, j = (i >> 7) & 15, kp = i >> 11;
    int g = lane >> 2, tig = lane & 3;
    int ks = kp * 2 + (q >> 1);
    int krow = ks * 8 + tig + 4 * (q & 1);
    int col = j * 8 + g;
    uint32_t h, l;
    split_tf32(W1[krow * CH + col], h, l);
    d_F1hi[i] = __uint_as_float(h);
    d_F1lo[i] = __uint_as_float(l);
    float w = (col < 64) ? Wmu[krow * 64 + col] : Wlv[krow * 64 + (col - 64)];
    split_tf32(w, h, l);
    d_Fmlhi[i] = __uint_as_float(h);
    d_Fmllo[i] = __uint_as_float(l);
}

// ---------------- detect width + zero counters ----------------
__global__ void k_detect_zero(const int* __restrict__ ei32) {
    int gid = blockIdx.x * 256 + threadIdx.x;
    if (gid < NN) d_cnt[gid] = 0;
    if (blockIdx.x == 0) {
        __shared__ int any;
        if (threadIdx.x == 0) any = 0;
        __syncthreads();
        for (int i = threadIdx.x; i < 4096; i += 256)
            if (ei32[2 * i + 1] != 0) any = 1;
        __syncthreads();
        if (threadIdx.x == 0) d_is64 = (any == 0) ? 1 : 0;
    }
}
__device__ __forceinline__ int edge_idx(const void* ei, int part, int e) {
    if (d_is64) return (int)((const long long*)ei)[(size_t)part * NE + e];
    return ((const int*)ei)[(size_t)part * NE + e];
}

__global__ void k_hist(const void* __restrict__ ei) {
    int i = blockIdx.x * 256 + threadIdx.x;
    if (i < NE) atomicAdd(&d_cnt[edge_idx(ei, 1, i)], 1);
}

// ---------------- 3xTF32 GEMM, cp.async 2-stage pipeline ----------
__device__ __forceinline__ void gemm_tc_loop(float* sPool,
                                             const float* __restrict__ Asrc,
                                             const float4* __restrict__ Fh4,
                                             const float4* __restrict__ Fl4,
                                             int row0, float acc[16][4]) {
    int tid  = threadIdx.x;
    int lane = tid & 31, warp = tid >> 5;
    int g = lane >> 2, tig = lane & 3;
    int ar = warp * 16 + g;
    uint32_t sbase = smem_u32(sPool);

    auto copy_chunk = [&](int c, int buf) {
        uint32_t aBuf = sbase + (buf * 2048) * 4;
        uint32_t hBuf = sbase + (4096 + buf * 2048) * 4;
        uint32_t lBuf = sbase + (8192 + buf * 2048) * 4;
#pragma unroll
        for (int i = 0; i < 2; i++) {        // A: 512 float4 (128 rows x 4 slots)
            int idx = tid + i * 256;
            int r = idx >> 2, s = idx & 3;
            int rg = row0 + r; rg = (rg < NN) ? rg : (NN - 1);
            const float* src = Asrc + (size_t)rg * CH + c * 16 + s * 4;
            int phys = r * 16 + ((s ^ ((r >> 1) & 3)) << 2);
            cpa16(aBuf + phys * 4, src);
        }
#pragma unroll
        for (int i = 0; i < 2; i++) {        // B frags: 512 float4 each
            int t = tid + i * 256;
            cpa16(hBuf + t * 16, Fh4 + (size_t)c * 512 + t);
            cpa16(lBuf + t * 16, Fl4 + (size_t)c * 512 + t);
        }
        asm volatile("cp.async.commit_group;" ::: "memory");
    };

    copy_chunk(0, 0);
    for (int c = 0; c < 8; c++) {
        if (c < 7) {
            copy_chunk(c + 1, (c + 1) & 1);
            asm volatile("cp.async.wait_group 1;" ::: "memory");
        } else {
            asm volatile("cp.async.wait_group 0;" ::: "memory");
        }
        __syncthreads();

        const float*  sA  = sPool + (c & 1) * 2048;
        const float4* sBh = (const float4*)(sPool + 4096 + (c & 1) * 2048);
        const float4* sBl = (const float4*)(sPool + 8192 + (c & 1) * 2048);
#define LDA(r, s) sA[(r) * 16 + (((((s) ^ (((r) >> 1) & 3))) << 2) | tig)]
        uint32_t ah0[4], al0[4], ah1[4], al1[4];
        split_tf32(LDA(ar, 0),     ah0[0], al0[0]);
        split_tf32(LDA(ar + 8, 0), ah0[1], al0[1]);
        split_tf32(LDA(ar, 1),     ah0[2], al0[2]);
        split_tf32(LDA(ar + 8, 1), ah0[3], al0[3]);
        split_tf32(LDA(ar, 2),     ah1[0], al1[0]);
        split_tf32(LDA(ar + 8, 2), ah1[1], al1[1]);
        split_tf32(LDA(ar, 3),     ah1[2], al1[2]);
        split_tf32(LDA(ar + 8, 3), ah1[3], al1[3]);
#undef LDA
#pragma unroll
        for (int j = 0; j < 16; j++) {
            float4 bh = sBh[j * 32 + lane];
            float4 bl = sBl[j * 32 + lane];
            mma_tf32(acc[j], ah0, __float_as_uint(bh.x), __float_as_uint(bh.y));
            mma_tf32(acc[j], ah0, __float_as_uint(bl.x), __float_as_uint(bl.y));
            mma_tf32(acc[j], al0, __float_as_uint(bh.x), __float_as_uint(bh.y));
            mma_tf32(acc[j], ah1, __float_as_uint(bh.z), __float_as_uint(bh.w));
            mma_tf32(acc[j], ah1, __float_as_uint(bl.z), __float_as_uint(bl.w));
            mma_tf32(acc[j], al1, __float_as_uint(bh.z), __float_as_uint(bh.w));
        }
        __syncthreads();
    }
}

// ---------------- GEMM1: d_A = x @ W1 (tensor cores, fp16 out) --------------
__global__ __launch_bounds__(256, 2) void k_gemm1_tc(const float* __restrict__ x) {
    __shared__ float sPool[12288];
    float acc[16][4];
#pragma unroll
    for (int j = 0; j < 16; j++) acc[j][0] = acc[j][1] = acc[j][2] = acc[j][3] = 0.f;
    int row0 = blockIdx.x * 128;
    gemm_tc_loop(sPool, x, (const float4*)d_F1hi, (const float4*)d_F1lo, row0, acc);

    int lane = threadIdx.x & 31, warp = threadIdx.x >> 5;
    int g = lane >> 2, tig = lane & 3;
    int r0 = row0 + warp * 16 + g, r1 = r0 + 8;
#pragma unroll
    for (int j = 0; j < 16; j++) {
        int col = j * 8 + 2 * tig;
        if (r0 < NN) {
            __half2 h = __floats2half2_rn(acc[j][0], acc[j][1]);
            *(__half2*)(d_A + (size_t)r0 * CH + col) = h;
        }
        if (r1 < NN) {
            __half2 h = __floats2half2_rn(acc[j][2], acc[j][3]);
            *(__half2*)(d_A + (size_t)r1 * CH + col) = h;
        }
    }
}

// ---------------- prefix sum (dis fused) ----------------
__global__ void k_scan_local() {
    __shared__ int s[1024];
    int tid = threadIdx.x;
    int gid = blockIdx.x * 1024 + tid;
    int v = (gid < NN) ? d_cnt[gid] : 0;
    if (gid < NN) d_dis[gid] = rsqrtf((float)v + 1.0f);
    s[tid] = v;
    __syncthreads();
    for (int o = 1; o < 1024; o <<= 1) {
        int t = (tid >= o) ? s[tid - o] : 0;
        __syncthreads();
        s[tid] += t;
        __syncthreads();
    }
    if (gid < NN) d_off[gid] = s[tid] - v;
    if (tid == 1023) d_blk[blockIdx.x] = s[1023];
}
__global__ void k_scan_blk() {
    __shared__ int s[128];
    int tid = threadIdx.x;
    int v = (tid < NBLK_SCAN) ? d_blk[tid] : 0;
    s[tid] = v;
    __syncthreads();
    for (int o = 1; o < 128; o <<= 1) {
        int t = (tid >= o) ? s[tid - o] : 0;
        __syncthreads();
        s[tid] += t;
        __syncthreads();
    }
    d_blkoff[tid] = s[tid] - v;
}
__global__ void k_scan_add() {
    int gid = blockIdx.x * 1024 + threadIdx.x;
    if (gid < NN) {
        int o = d_off[gid] + d_blkoff[blockIdx.x];
        d_off[gid] = o;
        d_pos[gid] = o;
    }
    if (gid == 0) d_off[NN] = NE;
}

__global__ void k_fill(const void* __restrict__ ei) {
    int e = blockIdx.x * 256 + threadIdx.x;
    if (e >= NE) return;
    int r = edge_idx(ei, 0, e);
    int c = edge_idx(ei, 1, e);
    int p = atomicAdd(&d_pos[c], 1);
    d_adj[p] = make_int2(r, __float_as_int(d_dis[r]));
}

// ---------------- CSR gathers (fp16 src, fp32 accumulate) ----------------
// phase 0: d_Cb(half) = relu(A * d_A(half) + b1)
__global__ __launch_bounds__(256) void k_gather0(const float* __restrict__ b1) {
    int node = (blockIdx.x * 256 + threadIdx.x) >> 5;
    if (node >= NN) return;
    int lane = threadIdx.x & 31;
    int beg = d_off[node], end = d_off[node + 1];
    float dc = d_dis[node];

    float4 acc = ld4h(d_A + (size_t)node * CH + lane * 4);
    acc.x *= dc; acc.y *= dc; acc.z *= dc; acc.w *= dc;

    for (int base = beg; base < end; base += 32) {
        int t = base + lane;
        int2 pr = (t < end) ? d_adj[t] : make_int2(0, 0);
        int n = min(32, end - base);
#pragma unroll 8
        for (int k = 0; k < n; k++) {
            int   j = __shfl_sync(0xffffffffu, pr.x, k);
            float w = __int_as_float(__shfl_sync(0xffffffffu, pr.y, k));
            float4 v = ld4h(d_A + (size_t)j * CH + lane * 4);
            acc.x = fmaf(w, v.x, acc.x);
            acc.y = fmaf(w, v.y, acc.y);
            acc.z = fmaf(w, v.z, acc.z);
            acc.w = fmaf(w, v.w, acc.w);
        }
    }
    float4 bias = ((const float4*)b1)[lane];
    acc.x = fmaxf(fmaf(acc.x, dc, bias.x), 0.f);
    acc.y = fmaxf(fmaf(acc.y, dc, bias.y), 0.f);
    acc.z = fmaxf(fmaf(acc.z, dc, bias.z), 0.f);
    acc.w = fmaxf(fmaf(acc.w, dc, bias.w), 0.f);
    st4h(d_Cb + (size_t)node * CH + lane * 4, acc);
}

// phase 1: d_B(float) = A * d_Cb(half)
__global__ __launch_bounds__(256) void k_gather1() {
    int node = (blockIdx.x * 256 + threadIdx.x) >> 5;
    if (node >= NN) return;
    int lane = threadIdx.x & 31;
    int beg = d_off[node], end = d_off[node + 1];
    float dc = d_dis[node];

    float4 acc = ld4h(d_Cb + (size_t)node * CH + lane * 4);
    acc.x *= dc; acc.y *= dc; acc.z *= dc; acc.w *= dc;

    for (int base = beg; base < end; base += 32) {
        int t = base + lane;
        int2 pr = (t < end) ? d_adj[t] : make_int2(0, 0);
        int n = min(32, end - base);
#pragma unroll 8
        for (int k = 0; k < n; k++) {
            int   j = __shfl_sync(0xffffffffu, pr.x, k);
            float w = __int_as_float(__shfl_sync(0xffffffffu, pr.y, k));
            float4 v = ld4h(d_Cb + (size_t)j * CH + lane * 4);
            acc.x = fmaf(w, v.x, acc.x);
            acc.y = fmaf(w, v.y, acc.y);
            acc.z = fmaf(w, v.z, acc.z);
            acc.w = fmaf(w, v.w, acc.w);
        }
    }
    acc.x *= dc; acc.y *= dc; acc.z *= dc; acc.w *= dc;
    ((float4*)(d_B + (size_t)node * CH))[lane] = acc;
}

// ---------------- final: [mu|lv] = g @ [Wmu|Wlv] (tensor) + reparam ----------
__global__ __launch_bounds__(256, 2) void k_final_tc(const float* __restrict__ bmu,
                                                     const float* __restrict__ blv,
                                                     const float* __restrict__ eps,
                                                     float* __restrict__ out) {
    __shared__ float sPool[12288];
    float acc[16][4];
#pragma unroll
    for (int j = 0; j < 16; j++) acc[j][0] = acc[j][1] = acc[j][2] = acc[j][3] = 0.f;
    int row0 = blockIdx.x * 128;
    gemm_tc_loop(sPool, d_B, (const float4*)d_Fmlhi, (const float4*)d_Fmllo, row0, acc);

    int lane = threadIdx.x & 31, warp = threadIdx.x >> 5;
    int g = lane >> 2, tig = lane & 3;
    int r0 = row0 + warp * 16 + g, r1 = r0 + 8;

    float* out_z  = out;
    float* out_mu = out + (size_t)NN * LAT;
    float* out_lv = out + 2 * (size_t)NN * LAT;

#pragma unroll
    for (int j = 0; j < 8; j++) {               // mu tiles; lv = tile j+8
        int col = j * 8 + 2 * tig;
        float2 bm = *(const float2*)(bmu + col);
        float2 bl = *(const float2*)(blv + col);
        if (r0 < NN) {
            float m0 = acc[j][0] + bm.x,     m1 = acc[j][1] + bm.y;
            float l0 = acc[j + 8][0] + bl.x, l1 = acc[j + 8][1] + bl.y;
            float2 ev = *(const float2*)(eps + (size_t)r0 * LAT + col);
            float z0 = m0 + ev.x * expf(0.5f * l0);
            float z1 = m1 + ev.y * expf(0.5f * l1);
            size_t o = (size_t)r0 * LAT + col;
            *(float2*)(out_mu + o) = make_float2(m0, m1);
            *(float2*)(out_lv + o) = make_float2(l0, l1);
            *(float2*)(out_z  + o) = make_float2(z0, z1);
        }
        if (r1 < NN) {
            float m0 = acc[j][2] + bm.x,     m1 = acc[j][3] + bm.y;
            float l0 = acc[j + 8][2] + bl.x, l1 = acc[j + 8][3] + bl.y;
            float2 ev = *(const float2*)(eps + (size_t)r1 * LAT + col);
            float z0 = m0 + ev.x * expf(0.5f * l0);
            float z1 = m1 + ev.y * expf(0.5f * l1);
            size_t o = (size_t)r1 * LAT + col;
            *(float2*)(out_mu + o) = make_float2(m0, m1);
            *(float2*)(out_lv + o) = make_float2(l0, l1);
            *(float2*)(out_z  + o) = make_float2(z0, z1);
        }
    }
}

// ---------------- launch: fork [wsplit->gemm1] parallel to CSR build ---------
extern "C" void kernel_launch(void* const* d_in, const int* in_sizes, int n_in,
                              void* d_out, int out_size) {
    const float* x   = (const float*)d_in[0];
    const void*  ei  = d_in[1];
    const float* W1  = (const float*)d_in[2];
    const float* b1  = (const float*)d_in[3];
    const float* Wmu = (const float*)d_in[4];
    const float* bmu = (const float*)d_in[5];
    const float* Wlv = (const float*)d_in[6];
    const float* blv = (const float*)d_in[7];
    const float* eps = (const float*)d_in[8];
    float* out = (float*)d_out;

    // One-time host-side resources (no device memory allocation).
    static cudaStream_t s2 = nullptr;
    static cudaEvent_t eFork = nullptr, eJoin = nullptr;
    if (s2 == nullptr) {
        cudaStreamCreateWithFlags(&s2, cudaStreamNonBlocking);
        cudaEventCreateWithFlags(&eFork, cudaEventDisableTiming);
        cudaEventCreateWithFlags(&eJoin, cudaEventDisableTiming);
    }

    // fork: GEMM branch on s2
    cudaEventRecord(eFork, 0);
    cudaStreamWaitEvent(s2, eFork, 0);
    k_wsplit<<<64, 256, 0, s2>>>(W1, Wmu, Wlv);
    k_gemm1_tc<<<GBLK, 256, 0, s2>>>(x);
    cudaEventRecord(eJoin, s2);

    // CSR build on main stream (independent of GEMM branch)
    k_detect_zero<<<(NN + 255) / 256, 256>>>((const int*)ei);
    k_hist<<<(NE + 255) / 256, 256>>>(ei);
    k_scan_local<<<NBLK_SCAN, 1024>>>();
    k_scan_blk<<<1, 128>>>();
    k_scan_add<<<NBLK_SCAN, 1024>>>();
    k_fill<<<(NE + 255) / 256, 256>>>(ei);

    // join: gathers need both d_A (s2) and CSR (main)
    cudaStreamWaitEvent(0, eJoin, 0);
    k_gather0<<<(NN * 32 + 255) / 256, 256>>>(b1);
    k_gather1<<<(NN * 32 + 255) / 256, 256>>>();
    k_final_tc<<<GBLK, 256>>>(bmu, blv, eps, out);
}

// round 12
// speedup vs baseline: 1.7623x; 1.1303x over previous
#include <cuda_runtime.h>
#include <cuda_fp16.h>
#include <cstdint>

#define NN  100000
#define NE  1600000
#define CH  128
#define LAT 64
#define NBLK_SCAN 98      // ceil(100000/1024)
#define GBLK 782          // ceil(NN/128) gemm blocks

// ---------------- scratch (no allocations allowed) ----------------
__device__ __half d_A[(size_t)NN * CH];   // h0 = x @ W1 (fp16)
__device__ __half d_Cb[(size_t)NN * CH];  // h = relu(conv1) (fp16)
__device__ __half d_B[(size_t)NN * CH];   // g = A * h (fp16, feeds final HMMA)
__device__ float  d_dis[NN];
__device__ int    d_cnt[NN];
__device__ int    d_off[NN + 1];
__device__ int    d_pos[NN];
__device__ int2   d_adj[NE];
__device__ int    d_blk[128], d_blkoff[128];
__device__ int    d_is64;
// W1 tf32 frags: idx = ((kp*16 + j)*32 + lane)*4 + q
__device__ float d_F1hi[CH * CH], d_F1lo[CH * CH];
// [Wmu|Wlv] fp16 frags: uint4 per (c,j,lane) = {b0hi, b1hi, b0lo, b1lo}
__device__ uint4 d_F16[8 * 16 * 32];

// ---------------- tf32 / fp16 helpers ----------------
__device__ __forceinline__ uint32_t f2tf32(float v) {
    uint32_t r; asm("cvt.rna.tf32.f32 %0, %1;" : "=r"(r) : "f"(v)); return r;
}
__device__ __forceinline__ void split_tf32(float v, uint32_t& hi, uint32_t& lo) {
    hi = f2tf32(v);
    lo = f2tf32(v - __uint_as_float(hi));
}
__device__ __forceinline__ void mma_tf32(float c[4], const uint32_t a[4],
                                         uint32_t b0, uint32_t b1) {
    asm volatile(
        "mma.sync.aligned.m16n8k8.row.col.f32.tf32.tf32.f32 "
        "{%0,%1,%2,%3},{%4,%5,%6,%7},{%8,%9},{%0,%1,%2,%3};"
        : "+f"(c[0]), "+f"(c[1]), "+f"(c[2]), "+f"(c[3])
        : "r"(a[0]), "r"(a[1]), "r"(a[2]), "r"(a[3]), "r"(b0), "r"(b1));
}
__device__ __forceinline__ void mma_f16(float c[4], uint32_t a0, uint32_t a1,
                                        uint32_t a2, uint32_t a3,
                                        uint32_t b0, uint32_t b1) {
    asm volatile(
        "mma.sync.aligned.m16n8k16.row.col.f32.f16.f16.f32 "
        "{%0,%1,%2,%3},{%4,%5,%6,%7},{%8,%9},{%0,%1,%2,%3};"
        : "+f"(c[0]), "+f"(c[1]), "+f"(c[2]), "+f"(c[3])
        : "r"(a0), "r"(a1), "r"(a2), "r"(a3), "r"(b0), "r"(b1));
}
__device__ __forceinline__ uint32_t smem_u32(const void* p) {
    return (uint32_t)__cvta_generic_to_shared(p);
}
__device__ __forceinline__ void cpa16(uint32_t dst, const void* src) {
    asm volatile("cp.async.cg.shared.global [%0], [%1], 16;" :: "r"(dst), "l"(src));
}
__device__ __forceinline__ float4 ld4h(const __half* p) {
    uint2 raw = *(const uint2*)p;
    __half2 a = *reinterpret_cast<__half2*>(&raw.x);
    __half2 b = *reinterpret_cast<__half2*>(&raw.y);
    float2 fa = __half22float2(a), fb = __half22float2(b);
    return make_float4(fa.x, fa.y, fb.x, fb.y);
}
__device__ __forceinline__ void st4h(__half* p, float4 v) {
    __half2 a = __floats2half2_rn(v.x, v.y);
    __half2 b = __floats2half2_rn(v.z, v.w);
    uint2 raw;
    raw.x = *reinterpret_cast<uint32_t*>(&a);
    raw.y = *reinterpret_cast<uint32_t*>(&b);
    *(uint2*)p = raw;
}
__device__ __forceinline__ uint32_t pack_h2(float x, float y) {
    __half2 h = __floats2half2_rn(x, y);
    return *reinterpret_cast<uint32_t*>(&h);
}

// ---------------- W split (one-time, tiny) ----------------
// i<16384: W1 tf32 frags. i<4096: [Wmu|Wlv] fp16 hi/lo frags.
__global__ void k_wsplit(const float* __restrict__ W1,
                         const float* __restrict__ Wmu,
                         const float* __restrict__ Wlv) {
    int i = blockIdx.x * 256 + threadIdx.x;
    if (i >= CH * CH) return;
    {
        int q = i & 3, lane = (i >> 2) & 31, j = (i >> 7) & 15, kp = i >> 11;
        int g = lane >> 2, tig = lane & 3;
        int ks = kp * 2 + (q >> 1);
        int krow = ks * 8 + tig + 4 * (q & 1);
        int col = j * 8 + g;
        uint32_t h, l;
        split_tf32(W1[krow * CH + col], h, l);
        d_F1hi[i] = __uint_as_float(h);
        d_F1lo[i] = __uint_as_float(l);
    }
    if (i < 4096) {
        int lane = i & 31, j = (i >> 5) & 15, c = i >> 9;
        int g = lane >> 2, tig = lane & 3;
        int col = j * 8 + g;
        int k0 = c * 16 + 2 * tig;
        float w[4];
#pragma unroll
        for (int t = 0; t < 4; t++) {
            int k = k0 + (t >> 1) * 8 + (t & 1);   // k0, k0+1, k0+8, k0+9
            w[t] = (col < 64) ? Wmu[k * 64 + col] : Wlv[k * 64 + (col - 64)];
        }
        float hi[4], lo[4];
#pragma unroll
        for (int t = 0; t < 4; t++) {
            __half h = __float2half_rn(w[t]);
            hi[t] = __half2float(h);
            lo[t] = w[t] - hi[t];
        }
        uint4 f;
        f.x = pack_h2(hi[0], hi[1]);
        f.y = pack_h2(hi[2], hi[3]);
        f.z = pack_h2(lo[0], lo[1]);
        f.w = pack_h2(lo[2], lo[3]);
        d_F16[i] = f;
    }
}

// ---------------- detect width + zero counters ----------------
__global__ void k_detect_zero(const int* __restrict__ ei32) {
    int gid = blockIdx.x * 256 + threadIdx.x;
    if (gid < NN) d_cnt[gid] = 0;
    if (blockIdx.x == 0) {
        __shared__ int any;
        if (threadIdx.x == 0) any = 0;
        __syncthreads();
        for (int i = threadIdx.x; i < 4096; i += 256)
            if (ei32[2 * i + 1] != 0) any = 1;
        __syncthreads();
        if (threadIdx.x == 0) d_is64 = (any == 0) ? 1 : 0;
    }
}
__device__ __forceinline__ int edge_idx(const void* ei, int part, int e) {
    if (d_is64) return (int)((const long long*)ei)[(size_t)part * NE + e];
    return ((const int*)ei)[(size_t)part * NE + e];
}

__global__ void k_hist(const void* __restrict__ ei) {
    int i = blockIdx.x * 256 + threadIdx.x;
    if (i < NE) atomicAdd(&d_cnt[edge_idx(ei, 1, i)], 1);
}

// ---------------- 3xTF32 GEMM (gemm1), cp.async 2-stage pipeline ----------
__device__ __forceinline__ void gemm_tc_loop(float* sPool,
                                             const float* __restrict__ Asrc,
                                             const float4* __restrict__ Fh4,
                                             const float4* __restrict__ Fl4,
                                             int row0, float acc[16][4]) {
    int tid  = threadIdx.x;
    int lane = tid & 31, warp = tid >> 5;
    int g = lane >> 2, tig = lane & 3;
    int ar = warp * 16 + g;
    uint32_t sbase = smem_u32(sPool);

    auto copy_chunk = [&](int c, int buf) {
        uint32_t aBuf = sbase + (buf * 2048) * 4;
        uint32_t hBuf = sbase + (4096 + buf * 2048) * 4;
        uint32_t lBuf = sbase + (8192 + buf * 2048) * 4;
#pragma unroll
        for (int i = 0; i < 2; i++) {
            int idx = tid + i * 256;
            int r = idx >> 2, s = idx & 3;
            int rg = row0 + r; rg = (rg < NN) ? rg : (NN - 1);
            const float* src = Asrc + (size_t)rg * CH + c * 16 + s * 4;
            int phys = r * 16 + ((s ^ ((r >> 1) & 3)) << 2);
            cpa16(aBuf + phys * 4, src);
        }
#pragma unroll
        for (int i = 0; i < 2; i++) {
            int t = tid + i * 256;
            cpa16(hBuf + t * 16, Fh4 + (size_t)c * 512 + t);
            cpa16(lBuf + t * 16, Fl4 + (size_t)c * 512 + t);
        }
        asm volatile("cp.async.commit_group;" ::: "memory");
    };

    copy_chunk(0, 0);
    for (int c = 0; c < 8; c++) {
        if (c < 7) {
            copy_chunk(c + 1, (c + 1) & 1);
            asm volatile("cp.async.wait_group 1;" ::: "memory");
        } else {
            asm volatile("cp.async.wait_group 0;" ::: "memory");
        }
        __syncthreads();

        const float*  sA  = sPool + (c & 1) * 2048;
        const float4* sBh = (const float4*)(sPool + 4096 + (c & 1) * 2048);
        const float4* sBl = (const float4*)(sPool + 8192 + (c & 1) * 2048);
#define LDA(r, s) sA[(r) * 16 + (((((s) ^ (((r) >> 1) & 3))) << 2) | tig)]
        uint32_t ah0[4], al0[4], ah1[4], al1[4];
        split_tf32(LDA(ar, 0),     ah0[0], al0[0]);
        split_tf32(LDA(ar + 8, 0), ah0[1], al0[1]);
        split_tf32(LDA(ar, 1),     ah0[2], al0[2]);
        split_tf32(LDA(ar + 8, 1), ah0[3], al0[3]);
        split_tf32(LDA(ar, 2),     ah1[0], al1[0]);
        split_tf32(LDA(ar + 8, 2), ah1[1], al1[1]);
        split_tf32(LDA(ar, 3),     ah1[2], al1[2]);
        split_tf32(LDA(ar + 8, 3), ah1[3], al1[3]);
#undef LDA
#pragma unroll
        for (int j = 0; j < 16; j++) {
            float4 bh = sBh[j * 32 + lane];
            float4 bl = sBl[j * 32 + lane];
            mma_tf32(acc[j], ah0, __float_as_uint(bh.x), __float_as_uint(bh.y));
            mma_tf32(acc[j], ah0, __float_as_uint(bl.x), __float_as_uint(bl.y));
            mma_tf32(acc[j], al0, __float_as_uint(bh.x), __float_as_uint(bh.y));
            mma_tf32(acc[j], ah1, __float_as_uint(bh.z), __float_as_uint(bh.w));
            mma_tf32(acc[j], ah1, __float_as_uint(bl.z), __float_as_uint(bl.w));
            mma_tf32(acc[j], al1, __float_as_uint(bh.z), __float_as_uint(bh.w));
        }
        __syncthreads();
    }
}

// ---------------- GEMM1: d_A = x @ W1 (tensor cores, fp16 out) --------------
__global__ __launch_bounds__(256, 2) void k_gemm1_tc(const float* __restrict__ x) {
    __shared__ float sPool[12288];
    float acc[16][4];
#pragma unroll
    for (int j = 0; j < 16; j++) acc[j][0] = acc[j][1] = acc[j][2] = acc[j][3] = 0.f;
    int row0 = blockIdx.x * 128;
    gemm_tc_loop(sPool, x, (const float4*)d_F1hi, (const float4*)d_F1lo, row0, acc);

    int lane = threadIdx.x & 31, warp = threadIdx.x >> 5;
    int g = lane >> 2, tig = lane & 3;
    int r0 = row0 + warp * 16 + g, r1 = r0 + 8;
#pragma unroll
    for (int j = 0; j < 16; j++) {
        int col = j * 8 + 2 * tig;
        if (r0 < NN) {
            __half2 h = __floats2half2_rn(acc[j][0], acc[j][1]);
            *(__half2*)(d_A + (size_t)r0 * CH + col) = h;
        }
        if (r1 < NN) {
            __half2 h = __floats2half2_rn(acc[j][2], acc[j][3]);
            *(__half2*)(d_A + (size_t)r1 * CH + col) = h;
        }
    }
}

// ---------------- prefix sum (dis fused) ----------------
__global__ void k_scan_local() {
    __shared__ int s[1024];
    int tid = threadIdx.x;
    int gid = blockIdx.x * 1024 + tid;
    int v = (gid < NN) ? d_cnt[gid] : 0;
    if (gid < NN) d_dis[gid] = rsqrtf((float)v + 1.0f);
    s[tid] = v;
    __syncthreads();
    for (int o = 1; o < 1024; o <<= 1) {
        int t = (tid >= o) ? s[tid - o] : 0;
        __syncthreads();
        s[tid] += t;
        __syncthreads();
    }
    if (gid < NN) d_off[gid] = s[tid] - v;
    if (tid == 1023) d_blk[blockIdx.x] = s[1023];
}
__global__ void k_scan_blk() {
    __shared__ int s[128];
    int tid = threadIdx.x;
    int v = (tid < NBLK_SCAN) ? d_blk[tid] : 0;
    s[tid] = v;
    __syncthreads();
    for (int o = 1; o < 128; o <<= 1) {
        int t = (tid >= o) ? s[tid - o] : 0;
        __syncthreads();
        s[tid] += t;
        __syncthreads();
    }
    d_blkoff[tid] = s[tid] - v;
}
__global__ void k_scan_add() {
    int gid = blockIdx.x * 1024 + threadIdx.x;
    if (gid < NN) {
        int o = d_off[gid] + d_blkoff[blockIdx.x];
        d_off[gid] = o;
        d_pos[gid] = o;
    }
    if (gid == 0) d_off[NN] = NE;
}

__global__ void k_fill(const void* __restrict__ ei) {
    int e = blockIdx.x * 256 + threadIdx.x;
    if (e >= NE) return;
    int r = edge_idx(ei, 0, e);
    int c = edge_idx(ei, 1, e);
    int p = atomicAdd(&d_pos[c], 1);
    d_adj[p] = make_int2(r, __float_as_int(d_dis[r]));
}

// ---------------- CSR gathers (fp16 src, fp32 accumulate) ----------------
__global__ __launch_bounds__(256) void k_gather0(const float* __restrict__ b1) {
    int node = (blockIdx.x * 256 + threadIdx.x) >> 5;
    if (node >= NN) return;
    int lane = threadIdx.x & 31;
    int beg = d_off[node], end = d_off[node + 1];
    float dc = d_dis[node];

    float4 acc = ld4h(d_A + (size_t)node * CH + lane * 4);
    acc.x *= dc; acc.y *= dc; acc.z *= dc; acc.w *= dc;

    for (int base = beg; base < end; base += 32) {
        int t = base + lane;
        int2 pr = (t < end) ? d_adj[t] : make_int2(0, 0);
        int n = min(32, end - base);
#pragma unroll 8
        for (int k = 0; k < n; k++) {
            int   j = __shfl_sync(0xffffffffu, pr.x, k);
            float w = __int_as_float(__shfl_sync(0xffffffffu, pr.y, k));
            float4 v = ld4h(d_A + (size_t)j * CH + lane * 4);
            acc.x = fmaf(w, v.x, acc.x);
            acc.y = fmaf(w, v.y, acc.y);
            acc.z = fmaf(w, v.z, acc.z);
            acc.w = fmaf(w, v.w, acc.w);
        }
    }
    float4 bias = ((const float4*)b1)[lane];
    acc.x = fmaxf(fmaf(acc.x, dc, bias.x), 0.f);
    acc.y = fmaxf(fmaf(acc.y, dc, bias.y), 0.f);
    acc.z = fmaxf(fmaf(acc.z, dc, bias.z), 0.f);
    acc.w = fmaxf(fmaf(acc.w, dc, bias.w), 0.f);
    st4h(d_Cb + (size_t)node * CH + lane * 4, acc);
}

__global__ __launch_bounds__(256) void k_gather1() {
    int node = (blockIdx.x * 256 + threadIdx.x) >> 5;
    if (node >= NN) return;
    int lane = threadIdx.x & 31;
    int beg = d_off[node], end = d_off[node + 1];
    float dc = d_dis[node];

    float4 acc = ld4h(d_Cb + (size_t)node * CH + lane * 4);
    acc.x *= dc; acc.y *= dc; acc.z *= dc; acc.w *= dc;

    for (int base = beg; base < end; base += 32) {
        int t = base + lane;
        int2 pr = (t < end) ? d_adj[t] : make_int2(0, 0);
        int n = min(32, end - base);
#pragma unroll 8
        for (int k = 0; k < n; k++) {
            int   j = __shfl_sync(0xffffffffu, pr.x, k);
            float w = __int_as_float(__shfl_sync(0xffffffffu, pr.y, k));
            float4 v = ld4h(d_Cb + (size_t)j * CH + lane * 4);
            acc.x = fmaf(w, v.x, acc.x);
            acc.y = fmaf(w, v.y, acc.y);
            acc.z = fmaf(w, v.z, acc.z);
            acc.w = fmaf(w, v.w, acc.w);
        }
    }
    acc.x *= dc; acc.y *= dc; acc.z *= dc; acc.w *= dc;
    st4h(d_B + (size_t)node * CH + lane * 4, acc);
}

// ---------------- final: [mu|lv] = g @ [Wmu|Wlv] (fp16 HMMA) + reparam -------
// A (d_B) fp16; W as hi/lo fp16 fragment pairs (2 MMAs = ~fp32 weight precision).
// A smem slot-XOR: 8-half slot s of row r stored at slot s ^ ((r>>2)&1).
__global__ __launch_bounds__(256, 2) void k_final_tc(const float* __restrict__ bmu,
                                                     const float* __restrict__ blv,
                                                     const float* __restrict__ eps,
                                                     float* __restrict__ out) {
    __shared__ uint4  sF[2][512];            // 16KB: W frags {b0hi,b1hi,b0lo,b1lo}
    __shared__ __half sA[2][128 * 16];       // 8KB: A tiles
    float acc[16][4];
#pragma unroll
    for (int j = 0; j < 16; j++) acc[j][0] = acc[j][1] = acc[j][2] = acc[j][3] = 0.f;
    int row0 = blockIdx.x * 128;
    int tid  = threadIdx.x;
    int lane = tid & 31, warp = tid >> 5;
    int g = lane >> 2, tig = lane & 3;
    int ar = warp * 16 + g;
    int b  = (ar >> 2) & 1;                  // same for ar and ar+8

    auto copy_chunk = [&](int c, int buf) {
        {   // A: 256 x 16B (128 rows x 2 slots of 8 halfs)
            int r = tid >> 1, s = tid & 1;
            int rg = row0 + r; rg = (rg < NN) ? rg : (NN - 1);
            const __half* src = d_B + (size_t)rg * CH + c * 16 + s * 8;
            uint32_t dst = smem_u32(&sA[buf][0]) + r * 32 + ((s ^ ((r >> 2) & 1)) * 16);
            cpa16(dst, src);
        }
#pragma unroll
        for (int i = 0; i < 2; i++) {        // W frags: 512 uint4
            int t = tid + i * 256;
            cpa16(smem_u32(&sF[buf][0]) + t * 16, d_F16 + c * 512 + t);
        }
        asm volatile("cp.async.commit_group;" ::: "memory");
    };

    copy_chunk(0, 0);
    for (int c = 0; c < 8; c++) {
        if (c < 7) {
            copy_chunk(c + 1, (c + 1) & 1);
            asm volatile("cp.async.wait_group 1;" ::: "memory");
        } else {
            asm volatile("cp.async.wait_group 0;" ::: "memory");
        }
        __syncthreads();

        const uint32_t* A32 = (const uint32_t*)&sA[c & 1][0];
        const uint4*    F   = &sF[c & 1][0];
        uint32_t a0 = A32[ar * 8       + ((0 ^ b) * 4 + tig)];
        uint32_t a1 = A32[(ar + 8) * 8 + ((0 ^ b) * 4 + tig)];
        uint32_t a2 = A32[ar * 8       + ((1 ^ b) * 4 + tig)];
        uint32_t a3 = A32[(ar + 8) * 8 + ((1 ^ b) * 4 + tig)];
#pragma unroll
        for (int j = 0; j < 16; j++) {
            uint4 f = F[j * 32 + lane];
            mma_f16(acc[j], a0, a1, a2, a3, f.x, f.y);
            mma_f16(acc[j], a0, a1, a2, a3, f.z, f.w);
        }
        __syncthreads();
    }

    int r0 = row0 + ar, r1 = r0 + 8;
    float* out_z  = out;
    float* out_mu = out + (size_t)NN * LAT;
    float* out_lv = out + 2 * (size_t)NN * LAT;

#pragma unroll
    for (int j = 0; j < 8; j++) {               // mu tiles; lv = tile j+8
        int col = j * 8 + 2 * tig;
        float2 bm = *(const float2*)(bmu + col);
        float2 bl = *(const float2*)(blv + col);
        if (r0 < NN) {
            float m0 = acc[j][0] + bm.x,     m1 = acc[j][1] + bm.y;
            float l0 = acc[j + 8][0] + bl.x, l1 = acc[j + 8][1] + bl.y;
            float2 ev = *(const float2*)(eps + (size_t)r0 * LAT + col);
            float z0 = m0 + ev.x * expf(0.5f * l0);
            float z1 = m1 + ev.y * expf(0.5f * l1);
            size_t o = (size_t)r0 * LAT + col;
            *(float2*)(out_mu + o) = make_float2(m0, m1);
            *(float2*)(out_lv + o) = make_float2(l0, l1);
            *(float2*)(out_z  + o) = make_float2(z0, z1);
        }
        if (r1 < NN) {
            float m0 = acc[j][2] + bm.x,     m1 = acc[j][3] + bm.y;
            float l0 = acc[j + 8][2] + bl.x, l1 = acc[j + 8][3] + bl.y;
            float2 ev = *(const float2*)(eps + (size_t)r1 * LAT + col);
            float z0 = m0 + ev.x * expf(0.5f * l0);
            float z1 = m1 + ev.y * expf(0.5f * l1);
            size_t o = (size_t)r1 * LAT + col;
            *(float2*)(out_mu + o) = make_float2(m0, m1);
            *(float2*)(out_lv + o) = make_float2(l0, l1);
            *(float2*)(out_z  + o) = make_float2(z0, z1);
        }
    }
}

// ---------------- launch: fork [wsplit->gemm1] parallel to CSR build ---------
extern "C" void kernel_launch(void* const* d_in, const int* in_sizes, int n_in,
                              void* d_out, int out_size) {
    const float* x   = (const float*)d_in[0];
    const void*  ei  = d_in[1];
    const float* W1  = (const float*)d_in[2];
    const float* b1  = (const float*)d_in[3];
    const float* Wmu = (const float*)d_in[4];
    const float* bmu = (const float*)d_in[5];
    const float* Wlv = (const float*)d_in[6];
    const float* blv = (const float*)d_in[7];
    const float* eps = (const float*)d_in[8];
    float* out = (float*)d_out;

    static cudaStream_t s2 = nullptr;
    static cudaEvent_t eFork = nullptr, eJoin = nullptr;
    if (s2 == nullptr) {
        cudaStreamCreateWithFlags(&s2, cudaStreamNonBlocking);
        cudaEventCreateWithFlags(&eFork, cudaEventDisableTiming);
        cudaEventCreateWithFlags(&eJoin, cudaEventDisableTiming);
    }

    // fork: GEMM branch on s2
    cudaEventRecord(eFork, 0);
    cudaStreamWaitEvent(s2, eFork, 0);
    k_wsplit<<<64, 256, 0, s2>>>(W1, Wmu, Wlv);
    k_gemm1_tc<<<GBLK, 256, 0, s2>>>(x);
    cudaEventRecord(eJoin, s2);

    // CSR build on main stream
    k_detect_zero<<<(NN + 255) / 256, 256>>>((const int*)ei);
    k_hist<<<(NE + 255) / 256, 256>>>(ei);
    k_scan_local<<<NBLK_SCAN, 1024>>>();
    k_scan_blk<<<1, 128>>>();
    k_scan_add<<<NBLK_SCAN, 1024>>>();
    k_fill<<<(NE + 255) / 256, 256>>>(ei);

    // join: gathers need both d_A (s2) and CSR (main)
    cudaStreamWaitEvent(0, eJoin, 0);
    k_gather0<<<(NN * 32 + 255) / 256, 256>>>(b1);
    k_gather1<<<(NN * 32 + 255) / 256, 256>>>();
    k_final_tc<<<GBLK, 256>>>(bmu, blv, eps, out);
}

// round 13
// speedup vs baseline: 1.9185x; 1.0886x over previous
#include <cuda_runtime.h>
#include <cuda_fp16.h>
#include <cstdint>

#define NN  100000
#define NE  1600000
#define CH  128
#define LAT 64
#define NBLK_SCAN 98      // ceil(100000/1024)
#define GBLK 782          // ceil(NN/128) gemm blocks

// ---------------- scratch (no allocations allowed) ----------------
__device__ __half d_A[(size_t)NN * CH];   // h0 = x @ W1 (fp16)
__device__ __half d_Cb[(size_t)NN * CH];  // h = relu(conv1) (fp16)
__device__ __half d_B[(size_t)NN * CH];   // g = A * h (fp16, feeds final HMMA)
__device__ float  d_dis[NN];
__device__ int    d_cnt[NN];
__device__ int    d_off[NN + 1];
__device__ int    d_pos[NN];
__device__ int2   d_adj[NE];
__device__ int    d_blk[128], d_blkoff[128];
__device__ int    d_is64;
// fp16 hi/lo weight fragments: uint4 per (c,j,lane) = {b0hi, b1hi, b0lo, b1lo}
__device__ uint4 d_F1[8 * 16 * 32];    // W1
__device__ uint4 d_F16[8 * 16 * 32];   // [Wmu|Wlv]

// ---------------- helpers ----------------
__device__ __forceinline__ void mma_f16(float c[4], uint32_t a0, uint32_t a1,
                                        uint32_t a2, uint32_t a3,
                                        uint32_t b0, uint32_t b1) {
    asm volatile(
        "mma.sync.aligned.m16n8k16.row.col.f32.f16.f16.f32 "
        "{%0,%1,%2,%3},{%4,%5,%6,%7},{%8,%9},{%0,%1,%2,%3};"
        : "+f"(c[0]), "+f"(c[1]), "+f"(c[2]), "+f"(c[3])
        : "r"(a0), "r"(a1), "r"(a2), "r"(a3), "r"(b0), "r"(b1));
}
__device__ __forceinline__ uint32_t smem_u32(const void* p) {
    return (uint32_t)__cvta_generic_to_shared(p);
}
__device__ __forceinline__ void cpa16(uint32_t dst, const void* src) {
    asm volatile("cp.async.cg.shared.global [%0], [%1], 16;" :: "r"(dst), "l"(src));
}
__device__ __forceinline__ float4 ld4h(const __half* p) {
    uint2 raw = *(const uint2*)p;
    __half2 a = *reinterpret_cast<__half2*>(&raw.x);
    __half2 b = *reinterpret_cast<__half2*>(&raw.y);
    float2 fa = __half22float2(a), fb = __half22float2(b);
    return make_float4(fa.x, fa.y, fb.x, fb.y);
}
__device__ __forceinline__ void st4h(__half* p, float4 v) {
    __half2 a = __floats2half2_rn(v.x, v.y);
    __half2 b = __floats2half2_rn(v.z, v.w);
    uint2 raw;
    raw.x = *reinterpret_cast<uint32_t*>(&a);
    raw.y = *reinterpret_cast<uint32_t*>(&b);
    *(uint2*)p = raw;
}
__device__ __forceinline__ uint32_t pack_h2(float x, float y) {
    __half2 h = __floats2half2_rn(x, y);
    return *reinterpret_cast<uint32_t*>(&h);
}

// ---------------- W split: hi/lo fp16 fragments for both GEMMs --------------
// frag index i -> (c = i>>9, j = (i>>5)&15, lane = i&31); col = j*8+g, k0 = c*16+2*tig
// b0 = {W[k0,col], W[k0+1,col]}, b1 = {W[k0+8,col], W[k0+9,col]}
__global__ void k_wsplit(const float* __restrict__ W1,
                         const float* __restrict__ Wmu,
                         const float* __restrict__ Wlv) {
    int i = blockIdx.x * 256 + threadIdx.x;
    if (i >= 4096) return;
    int lane = i & 31, j = (i >> 5) & 15, c = i >> 9;
    int g = lane >> 2, tig = lane & 3;
    int col = j * 8 + g;
    int k0 = c * 16 + 2 * tig;

    float w1v[4], wmv[4];
#pragma unroll
    for (int t = 0; t < 4; t++) {
        int k = k0 + (t >> 1) * 8 + (t & 1);   // k0, k0+1, k0+8, k0+9
        w1v[t] = W1[k * CH + col];
        wmv[t] = (col < 64) ? Wmu[k * 64 + col] : Wlv[k * 64 + (col - 64)];
    }
    float h1[4], l1[4], hm[4], lm[4];
#pragma unroll
    for (int t = 0; t < 4; t++) {
        __half a = __float2half_rn(w1v[t]);
        h1[t] = __half2float(a); l1[t] = w1v[t] - h1[t];
        __half b = __float2half_rn(wmv[t]);
        hm[t] = __half2float(b); lm[t] = wmv[t] - hm[t];
    }
    uint4 f1, fm;
    f1.x = pack_h2(h1[0], h1[1]); f1.y = pack_h2(h1[2], h1[3]);
    f1.z = pack_h2(l1[0], l1[1]); f1.w = pack_h2(l1[2], l1[3]);
    fm.x = pack_h2(hm[0], hm[1]); fm.y = pack_h2(hm[2], hm[3]);
    fm.z = pack_h2(lm[0], lm[1]); fm.w = pack_h2(lm[2], lm[3]);
    d_F1[i]  = f1;
    d_F16[i] = fm;
}

// ---------------- detect width + zero counters ----------------
__global__ void k_detect_zero(const int* __restrict__ ei32) {
    int gid = blockIdx.x * 256 + threadIdx.x;
    if (gid < NN) d_cnt[gid] = 0;
    if (blockIdx.x == 0) {
        __shared__ int any;
        if (threadIdx.x == 0) any = 0;
        __syncthreads();
        for (int i = threadIdx.x; i < 4096; i += 256)
            if (ei32[2 * i + 1] != 0) any = 1;
        __syncthreads();
        if (threadIdx.x == 0) d_is64 = (any == 0) ? 1 : 0;
    }
}
__device__ __forceinline__ int edge_idx(const void* ei, int part, int e) {
    if (d_is64) return (int)((const long long*)ei)[(size_t)part * NE + e];
    return ((const int*)ei)[(size_t)part * NE + e];
}

__global__ void k_hist(const void* __restrict__ ei) {
    int i = blockIdx.x * 256 + threadIdx.x;
    if (i < NE) atomicAdd(&d_cnt[edge_idx(ei, 1, i)], 1);
}

// ---------------- GEMM1: d_A = x @ W1 (fp16 HMMA, hi/lo W) ------------------
// A staged fp32 (swizzled), converted to packed half2 at register load.
__global__ __launch_bounds__(256, 2) void k_gemm1_tc(const float* __restrict__ x) {
    __shared__ float sA[2][2048];            // 16KB: 128 rows x 16 floats
    __shared__ uint4 sW[2][512];             // 16KB: W1 frags
    float acc[16][4];
#pragma unroll
    for (int j = 0; j < 16; j++) acc[j][0] = acc[j][1] = acc[j][2] = acc[j][3] = 0.f;
    int row0 = blockIdx.x * 128;
    int tid  = threadIdx.x;
    int lane = tid & 31, warp = tid >> 5;
    int g = lane >> 2, tig = lane & 3;
    int ar = warp * 16 + g;

    auto copy_chunk = [&](int c, int buf) {
#pragma unroll
        for (int i = 0; i < 2; i++) {        // A: 512 float4, swizzled
            int idx = tid + i * 256;
            int r = idx >> 2, s = idx & 3;
            int rg = row0 + r; rg = (rg < NN) ? rg : (NN - 1);
            const float* src = x + (size_t)rg * CH + c * 16 + s * 4;
            int phys = r * 16 + ((s ^ ((r >> 1) & 3)) << 2);
            cpa16(smem_u32(&sA[buf][0]) + phys * 4, src);
        }
#pragma unroll
        for (int i = 0; i < 2; i++) {        // W frags: 512 uint4
            int t = tid + i * 256;
            cpa16(smem_u32(&sW[buf][0]) + t * 16, d_F1 + c * 512 + t);
        }
        asm volatile("cp.async.commit_group;" ::: "memory");
    };

    copy_chunk(0, 0);
    for (int c = 0; c < 8; c++) {
        if (c < 7) {
            copy_chunk(c + 1, (c + 1) & 1);
            asm volatile("cp.async.wait_group 1;" ::: "memory");
        } else {
            asm volatile("cp.async.wait_group 0;" ::: "memory");
        }
        __syncthreads();

        const float* A = &sA[c & 1][0];
        const uint4* F = &sW[c & 1][0];
#define LDA(r, k) A[(r) * 16 + (((((k) >> 2) ^ (((r) >> 1) & 3))) << 2 | ((k) & 3))]
        uint32_t a0 = pack_h2(LDA(ar, 2 * tig),         LDA(ar, 2 * tig + 1));
        uint32_t a1 = pack_h2(LDA(ar + 8, 2 * tig),     LDA(ar + 8, 2 * tig + 1));
        uint32_t a2 = pack_h2(LDA(ar, 8 + 2 * tig),     LDA(ar, 8 + 2 * tig + 1));
        uint32_t a3 = pack_h2(LDA(ar + 8, 8 + 2 * tig), LDA(ar + 8, 8 + 2 * tig + 1));
#undef LDA
#pragma unroll
        for (int j = 0; j < 16; j++) {
            uint4 f = F[j * 32 + lane];
            mma_f16(acc[j], a0, a1, a2, a3, f.x, f.y);
            mma_f16(acc[j], a0, a1, a2, a3, f.z, f.w);
        }
        __syncthreads();
    }

    int r0 = row0 + ar, r1 = r0 + 8;
#pragma unroll
    for (int j = 0; j < 16; j++) {
        int col = j * 8 + 2 * tig;
        if (r0 < NN) {
            __half2 h = __floats2half2_rn(acc[j][0], acc[j][1]);
            *(__half2*)(d_A + (size_t)r0 * CH + col) = h;
        }
        if (r1 < NN) {
            __half2 h = __floats2half2_rn(acc[j][2], acc[j][3]);
            *(__half2*)(d_A + (size_t)r1 * CH + col) = h;
        }
    }
}

// ---------------- prefix sum (dis fused) ----------------
__global__ void k_scan_local() {
    __shared__ int s[1024];
    int tid = threadIdx.x;
    int gid = blockIdx.x * 1024 + tid;
    int v = (gid < NN) ? d_cnt[gid] : 0;
    if (gid < NN) d_dis[gid] = rsqrtf((float)v + 1.0f);
    s[tid] = v;
    __syncthreads();
    for (int o = 1; o < 1024; o <<= 1) {
        int t = (tid >= o) ? s[tid - o] : 0;
        __syncthreads();
        s[tid] += t;
        __syncthreads();
    }
    if (gid < NN) d_off[gid] = s[tid] - v;
    if (tid == 1023) d_blk[blockIdx.x] = s[1023];
}
__global__ void k_scan_blk() {
    __shared__ int s[128];
    int tid = threadIdx.x;
    int v = (tid < NBLK_SCAN) ? d_blk[tid] : 0;
    s[tid] = v;
    __syncthreads();
    for (int o = 1; o < 128; o <<= 1) {
        int t = (tid >= o) ? s[tid - o] : 0;
        __syncthreads();
        s[tid] += t;
        __syncthreads();
    }
    d_blkoff[tid] = s[tid] - v;
}
__global__ void k_scan_add() {
    int gid = blockIdx.x * 1024 + threadIdx.x;
    if (gid < NN) {
        int o = d_off[gid] + d_blkoff[blockIdx.x];
        d_off[gid] = o;
        d_pos[gid] = o;
    }
    if (gid == 0) d_off[NN] = NE;
}

__global__ void k_fill(const void* __restrict__ ei) {
    int e = blockIdx.x * 256 + threadIdx.x;
    if (e >= NE) return;
    int r = edge_idx(ei, 0, e);
    int c = edge_idx(ei, 1, e);
    int p = atomicAdd(&d_pos[c], 1);
    d_adj[p] = make_int2(r, __float_as_int(d_dis[r]));
}

// ---------------- CSR gathers (fp16 src, fp32 accumulate) ----------------
__global__ __launch_bounds__(256) void k_gather0(const float* __restrict__ b1) {
    int node = (blockIdx.x * 256 + threadIdx.x) >> 5;
    if (node >= NN) return;
    int lane = threadIdx.x & 31;
    int beg = d_off[node], end = d_off[node + 1];
    float dc = d_dis[node];

    float4 acc = ld4h(d_A + (size_t)node * CH + lane * 4);
    acc.x *= dc; acc.y *= dc; acc.z *= dc; acc.w *= dc;

    for (int base = beg; base < end; base += 32) {
        int t = base + lane;
        int2 pr = (t < end) ? d_adj[t] : make_int2(0, 0);
        int n = min(32, end - base);
#pragma unroll 8
        for (int k = 0; k < n; k++) {
            int   j = __shfl_sync(0xffffffffu, pr.x, k);
            float w = __int_as_float(__shfl_sync(0xffffffffu, pr.y, k));
            float4 v = ld4h(d_A + (size_t)j * CH + lane * 4);
            acc.x = fmaf(w, v.x, acc.x);
            acc.y = fmaf(w, v.y, acc.y);
            acc.z = fmaf(w, v.z, acc.z);
            acc.w = fmaf(w, v.w, acc.w);
        }
    }
    float4 bias = ((const float4*)b1)[lane];
    acc.x = fmaxf(fmaf(acc.x, dc, bias.x), 0.f);
    acc.y = fmaxf(fmaf(acc.y, dc, bias.y), 0.f);
    acc.z = fmaxf(fmaf(acc.z, dc, bias.z), 0.f);
    acc.w = fmaxf(fmaf(acc.w, dc, bias.w), 0.f);
    st4h(d_Cb + (size_t)node * CH + lane * 4, acc);
}

__global__ __launch_bounds__(256) void k_gather1() {
    int node = (blockIdx.x * 256 + threadIdx.x) >> 5;
    if (node >= NN) return;
    int lane = threadIdx.x & 31;
    int beg = d_off[node], end = d_off[node + 1];
    float dc = d_dis[node];

    float4 acc = ld4h(d_Cb + (size_t)node * CH + lane * 4);
    acc.x *= dc; acc.y *= dc; acc.z *= dc; acc.w *= dc;

    for (int base = beg; base < end; base += 32) {
        int t = base + lane;
        int2 pr = (t < end) ? d_adj[t] : make_int2(0, 0);
        int n = min(32, end - base);
#pragma unroll 8
        for (int k = 0; k < n; k++) {
            int   j = __shfl_sync(0xffffffffu, pr.x, k);
            float w = __int_as_float(__shfl_sync(0xffffffffu, pr.y, k));
            float4 v = ld4h(d_Cb + (size_t)j * CH + lane * 4);
            acc.x = fmaf(w, v.x, acc.x);
            acc.y = fmaf(w, v.y, acc.y);
            acc.z = fmaf(w, v.z, acc.z);
            acc.w = fmaf(w, v.w, acc.w);
        }
    }
    acc.x *= dc; acc.y *= dc; acc.z *= dc; acc.w *= dc;
    st4h(d_B + (size_t)node * CH + lane * 4, acc);
}

// ---------------- final: [mu|lv] = g @ [Wmu|Wlv] (fp16 HMMA) + reparam -------
__global__ __launch_bounds__(256, 2) void k_final_tc(const float* __restrict__ bmu,
                                                     const float* __restrict__ blv,
                                                     const float* __restrict__ eps,
                                                     float* __restrict__ out) {
    __shared__ uint4  sF[2][512];            // 16KB: W frags
    __shared__ __half sA[2][128 * 16];       // 8KB: A tiles
    float acc[16][4];
#pragma unroll
    for (int j = 0; j < 16; j++) acc[j][0] = acc[j][1] = acc[j][2] = acc[j][3] = 0.f;
    int row0 = blockIdx.x * 128;
    int tid  = threadIdx.x;
    int lane = tid & 31, warp = tid >> 5;
    int g = lane >> 2, tig = lane & 3;
    int ar = warp * 16 + g;
    int b  = (ar >> 2) & 1;

    auto copy_chunk = [&](int c, int buf) {
        {   // A: 256 x 16B (128 rows x 2 slots of 8 halfs)
            int r = tid >> 1, s = tid & 1;
            int rg = row0 + r; rg = (rg < NN) ? rg : (NN - 1);
            const __half* src = d_B + (size_t)rg * CH + c * 16 + s * 8;
            uint32_t dst = smem_u32(&sA[buf][0]) + r * 32 + ((s ^ ((r >> 2) & 1)) * 16);
            cpa16(dst, src);
        }
#pragma unroll
        for (int i = 0; i < 2; i++) {
            int t = tid + i * 256;
            cpa16(smem_u32(&sF[buf][0]) + t * 16, d_F16 + c * 512 + t);
        }
        asm volatile("cp.async.commit_group;" ::: "memory");
    };

    copy_chunk(0, 0);
    for (int c = 0; c < 8; c++) {
        if (c < 7) {
            copy_chunk(c + 1, (c + 1) & 1);
            asm volatile("cp.async.wait_group 1;" ::: "memory");
        } else {
            asm volatile("cp.async.wait_group 0;" ::: "memory");
        }
        __syncthreads();

        const uint32_t* A32 = (const uint32_t*)&sA[c & 1][0];
        const uint4*    F   = &sF[c & 1][0];
        uint32_t a0 = A32[ar * 8       + ((0 ^ b) * 4 + tig)];
        uint32_t a1 = A32[(ar + 8) * 8 + ((0 ^ b) * 4 + tig)];
        uint32_t a2 = A32[ar * 8       + ((1 ^ b) * 4 + tig)];
        uint32_t a3 = A32[(ar + 8) * 8 + ((1 ^ b) * 4 + tig)];
#pragma unroll
        for (int j = 0; j < 16; j++) {
            uint4 f = F[j * 32 + lane];
            mma_f16(acc[j], a0, a1, a2, a3, f.x, f.y);
            mma_f16(acc[j], a0, a1, a2, a3, f.z, f.w);
        }
        __syncthreads();
    }

    int r0 = row0 + ar, r1 = r0 + 8;
    float* out_z  = out;
    float* out_mu = out + (size_t)NN * LAT;
    float* out_lv = out + 2 * (size_t)NN * LAT;

#pragma unroll
    for (int j = 0; j < 8; j++) {               // mu tiles; lv = tile j+8
        int col = j * 8 + 2 * tig;
        float2 bm = *(const float2*)(bmu + col);
        float2 bl = *(const float2*)(blv + col);
        if (r0 < NN) {
            float m0 = acc[j][0] + bm.x,     m1 = acc[j][1] + bm.y;
            float l0 = acc[j + 8][0] + bl.x, l1 = acc[j + 8][1] + bl.y;
            float2 ev = *(const float2*)(eps + (size_t)r0 * LAT + col);
            float z0 = m0 + ev.x * expf(0.5f * l0);
            float z1 = m1 + ev.y * expf(0.5f * l1);
            size_t o = (size_t)r0 * LAT + col;
            *(float2*)(out_mu + o) = make_float2(m0, m1);
            *(float2*)(out_lv + o) = make_float2(l0, l1);
            *(float2*)(out_z  + o) = make_float2(z0, z1);
        }
        if (r1 < NN) {
            float m0 = acc[j][2] + bm.x,     m1 = acc[j][3] + bm.y;
            float l0 = acc[j + 8][2] + bl.x, l1 = acc[j + 8][3] + bl.y;
            float2 ev = *(const float2*)(eps + (size_t)r1 * LAT + col);
            float z0 = m0 + ev.x * expf(0.5f * l0);
            float z1 = m1 + ev.y * expf(0.5f * l1);
            size_t o = (size_t)r1 * LAT + col;
            *(float2*)(out_mu + o) = make_float2(m0, m1);
            *(float2*)(out_lv + o) = make_float2(l0, l1);
            *(float2*)(out_z  + o) = make_float2(z0, z1);
        }
    }
}

// ---------------- launch: fork [wsplit->gemm1] parallel to CSR build ---------
extern "C" void kernel_launch(void* const* d_in, const int* in_sizes, int n_in,
                              void* d_out, int out_size) {
    const float* x   = (const float*)d_in[0];
    const void*  ei  = d_in[1];
    const float* W1  = (const float*)d_in[2];
    const float* b1  = (const float*)d_in[3];
    const float* Wmu = (const float*)d_in[4];
    const float* bmu = (const float*)d_in[5];
    const float* Wlv = (const float*)d_in[6];
    const float* blv = (const float*)d_in[7];
    const float* eps = (const float*)d_in[8];
    float* out = (float*)d_out;

    static cudaStream_t s2 = nullptr;
    static cudaEvent_t eFork = nullptr, eJoin = nullptr;
    if (s2 == nullptr) {
        cudaStreamCreateWithFlags(&s2, cudaStreamNonBlocking);
        cudaEventCreateWithFlags(&eFork, cudaEventDisableTiming);
        cudaEventCreateWithFlags(&eJoin, cudaEventDisableTiming);
    }

    // fork: GEMM branch on s2
    cudaEventRecord(eFork, 0);
    cudaStreamWaitEvent(s2, eFork, 0);
    k_wsplit<<<16, 256, 0, s2>>>(W1, Wmu, Wlv);
    k_gemm1_tc<<<GBLK, 256, 0, s2>>>(x);
    cudaEventRecord(eJoin, s2);

    // CSR build on main stream
    k_detect_zero<<<(NN + 255) / 256, 256>>>((const int*)ei);
    k_hist<<<(NE + 255) / 256, 256>>>(ei);
    k_scan_local<<<NBLK_SCAN, 1024>>>();
    k_scan_blk<<<1, 128>>>();
    k_scan_add<<<NBLK_SCAN, 1024>>>();
    k_fill<<<(NE + 255) / 256, 256>>>(ei);

    // join: gathers need both d_A (s2) and CSR (main)
    cudaStreamWaitEvent(0, eJoin, 0);
    k_gather0<<<(NN * 32 + 255) / 256, 256>>>(b1);
    k_gather1<<<(NN * 32 + 255) / 256, 256>>>();
    k_final_tc<<<GBLK, 256>>>(bmu, blv, eps, out);
}